// round 6
// baseline (speedup 1.0000x reference)
#include <cuda_runtime.h>

#define BB 2
#define NN 40000
#define EE 400000
#define RR 64
#define DD 64
#define LLAYERS 6
#define MASKW 1250  // (NN+31)/32

// Scratch (allocation-free rule: __device__ globals)
__device__ __align__(16) float g_x[BB * NN * DD];    // 20.5 MB
__device__ __align__(16) float g_agg[BB * NN * DD];  // 20.5 MB (invariant: all-zero at launch entry/exit)
__device__ __align__(16) float g_rel[BB * RR * DD];
__device__ __align__(16) float g_query[BB * DD];
__device__ __align__(16) float g_qpart[BB * 2 * DD];
__device__ unsigned g_mask[BB * MASKW];  // bit set <=> node is in g_list
__device__ int g_list[BB * NN];          // persistent, monotone across layers
__device__ int g_count[BB];
__device__ int g_dense;  // 1 => zero rows would produce nonzero output

// ---------------------------------------------------------------------------
// prep: masks, query, dense flag, list seed {h}, qpart
// ---------------------------------------------------------------------------
__global__ void prep_kernel(const float* __restrict__ rel_reps,
                            const int* __restrict__ r_index,
                            const int* __restrict__ h_index,
                            const float* __restrict__ mlp_w,
                            const float* __restrict__ mlp_b,
                            const float* __restrict__ lin_b,
                            const float* __restrict__ ln_g,
                            const float* __restrict__ ln_b) {
    __shared__ float q_s[BB * DD];
    int t = threadIdx.x;  // 256
    for (int i = t; i < BB * MASKW; i += 256) g_mask[i] = 0u;
    if (t < BB * DD) {
        int b = t / DD, d = t % DD;
        float v = rel_reps[(b * RR + r_index[b]) * DD + d];
        g_query[t] = v;
        q_s[t] = v;
    }
    if (t == 0) {
        int dense = 0;
        for (int l = 0; l < LLAYERS; l++) {
            const float* lb = lin_b + l * DD;
            float mu = 0.f;
            for (int d = 0; d < DD; d++) mu += lb[d];
            mu *= (1.f / DD);
            float var = 0.f;
            for (int d = 0; d < DD; d++) {
                float dv = lb[d] - mu;
                var += dv * dv;
            }
            var *= (1.f / DD);
            float inv = rsqrtf(var + 1e-5f);
            for (int d = 0; d < DD; d++) {
                float o = (lb[d] - mu) * inv * ln_g[l * DD + d] + ln_b[l * DD + d];
                if (o > 0.f) dense = 1;
            }
        }
        g_dense = dense;
    }
    __syncthreads();
    if (t < BB) {
        int h = h_index[t];
        g_mask[t * MASKW + (h >> 5)] = 1u << (h & 31);
        g_count[t] = g_dense ? NN : 1;
        g_list[t * NN] = h;
    }
    int b = t / 128, e = t % 128;
    float acc = mlp_b[e];
#pragma unroll
    for (int k = 0; k < DD; k++)
        acc = fmaf(q_s[b * DD + k], mlp_w[(DD + k) * 128 + e], acc);
    g_qpart[b * 128 + e] = acc;
}

// ---------------------------------------------------------------------------
// init x: zeros everywhere, query at h_index[b].
// Dense fallback: also fill identity list + all-ones mask.
// ---------------------------------------------------------------------------
__global__ void init_x(const int* __restrict__ h_index) {
    int gid = blockIdx.x * 256 + threadIdx.x;
    const int per_b = NN * DD / 4;
    if (gid >= BB * per_b) return;
    if (g_dense) {
        if (gid < BB * NN) g_list[gid] = gid % NN;
        if (gid < BB * MASKW) g_mask[gid] = 0xffffffffu;
    }
    int b = gid / per_b;
    int r = gid - b * per_b;
    int n = r >> 4;
    int d4 = r & 15;
    float4 v = make_float4(0.f, 0.f, 0.f, 0.f);
    if (n == __ldg(&h_index[b]))
        v = *(const float4*)&g_query[b * DD + d4 * 4];
    ((float4*)g_x)[gid] = v;
}

// ---------------------------------------------------------------------------
// per-layer relation projection + boundary row agg[b,h]=query
// ---------------------------------------------------------------------------
__global__ void relproj_kernel(const float* __restrict__ rel_reps,
                               const float* __restrict__ pw1,
                               const float* __restrict__ pb1,
                               const float* __restrict__ pw2,
                               const float* __restrict__ pb2,
                               const int* __restrict__ h_index, int l) {
    int br = blockIdx.x;
    int b = br >> 6;
    int e = threadIdx.x;  // 64
    __shared__ float in_s[DD];
    __shared__ float hid_s[DD];
    in_s[e] = rel_reps[br * DD + e];
    __syncthreads();
    const float* W1 = pw1 + l * DD * DD;
    float acc = pb1[l * DD + e];
#pragma unroll 16
    for (int k = 0; k < DD; k++) acc = fmaf(in_s[k], W1[k * DD + e], acc);
    hid_s[e] = fmaxf(acc, 0.f);
    __syncthreads();
    const float* W2 = pw2 + l * DD * DD;
    float acc2 = pb2[l * DD + e];
#pragma unroll 16
    for (int k = 0; k < DD; k++) acc2 = fmaf(hid_s[k], W2[k * DD + e], acc2);
    g_rel[br * DD + e] = acc2;

    if ((br & 63) == 0) {
        int h = __ldg(&h_index[b]);
        g_agg[(b * NN + h) * DD + e] = g_query[b * DD + e];
    }
}

// ---------------------------------------------------------------------------
// message: 4 edges/thread. Inactive src => one mask probe. Active:
// agg[dst] += x[src]*rel[type]; newly-activated dsts get appended to the
// persistent list (warp-aggregated, exactly-once via atomicOr old value).
// No early return: ballot/shfl run convergent.
// ---------------------------------------------------------------------------
__global__ void __launch_bounds__(256, 4)
message_kernel(const int* __restrict__ edge_index,
               const int* __restrict__ edge_type) {
    const unsigned FULL = 0xffffffffu;
    int gid = blockIdx.x * 256 + threadIdx.x;
    const int per_b = EE / 4;  // 100000
    bool valid = gid < BB * per_b;
    int b = (gid >= per_b) ? 1 : 0;
    int e4 = gid - b * per_b;
    int4 s4 = make_int4(0, 0, 0, 0);
    if (valid) s4 = __ldg((const int4*)edge_index + e4);
    int srcs[4] = {s4.x, s4.y, s4.z, s4.w};
    const unsigned* mask = g_mask + b * MASKW;
    int lane = threadIdx.x & 31;
#pragma unroll
    for (int j = 0; j < 4; j++) {
        int src = srcs[j];
        bool act = valid && ((mask[src >> 5] >> (src & 31)) & 1u);
        int dst = 0, ty = 0;
        bool newd = false;
        if (act) {
            int e = e4 * 4 + j;
            dst = __ldg(&edge_index[EE + e]);
            ty = __ldg(&edge_type[e]);
            unsigned bitm = 1u << (dst & 31);
            unsigned* wp = &g_mask[b * MASKW + (dst >> 5)];
            if (!(*(volatile unsigned*)wp & bitm)) {
                unsigned old = atomicOr(wp, bitm);
                newd = !(old & bitm);
            }
        }
        // warp-aggregated append of newly activated dsts (convergent point)
        unsigned ball = __ballot_sync(FULL, newd);
        if (ball) {
            unsigned peers = __match_any_sync(FULL, b) & ball;
            int leader = __ffs(peers) - 1;  // valid where peers != 0
            int pos0 = 0;
            if (newd && lane == leader)
                pos0 = atomicAdd(&g_count[b], __popc(peers));
            pos0 = __shfl_sync(FULL, pos0, leader < 0 ? 0 : leader);
            if (newd)
                g_list[b * NN + pos0 + __popc(peers & ((1u << lane) - 1u))] =
                    dst;
        }
        if (act) {
            const float4* xr = (const float4*)(g_x + (b * NN + src) * DD);
            const float4* rr = (const float4*)(g_rel + (b * RR + ty) * DD);
            float* ar = g_agg + (b * NN + dst) * DD;
#pragma unroll
            for (int h = 0; h < 2; h++) {
                float4 xv[8];
#pragma unroll
                for (int c = 0; c < 8; c++) xv[c] = xr[h * 8 + c];
#pragma unroll
                for (int c = 0; c < 8; c++) {
                    float4 x = xv[c];
                    if (x.x == 0.f && x.y == 0.f && x.z == 0.f && x.w == 0.f)
                        continue;
                    float4 rv = __ldg(&rr[h * 8 + c]);
                    asm volatile(
                        "red.global.add.v4.f32 [%0], {%1,%2,%3,%4};" ::"l"(
                            ar + (h * 8 + c) * 4),
                        "f"(x.x * rv.x), "f"(x.y * rv.y), "f"(x.z * rv.z),
                        "f"(x.w * rv.w)
                        : "memory");
                }
            }
        }
    }
}

// ---------------------------------------------------------------------------
// fused linear: x = relu(LN(cat(x,agg)@W + b)) + x for list rows; agg->0.
// Block: 128 list rows x 64 dims; 256 threads, 4x8 register tile.
// smem 96KB => 2 blocks/SM = 16 warps/SM; 48B smem per 32 FMA.
// ---------------------------------------------------------------------------
__global__ void __launch_bounds__(256)
linear_kernel(const float* __restrict__ lin_w,
              const float* __restrict__ lin_b,
              const float* __restrict__ ln_g,
              const float* __restrict__ ln_b, int l) {
    extern __shared__ float smem[];
    float* W_s = smem;               // [128][64]  = 32KB
    float* cat_s = smem + 128 * 64;  // [128 k][128 rows] = 64KB
    __shared__ int idx_s[128];
    int b = blockIdx.y;
    int base = blockIdx.x * 128;
    int t = threadIdx.x;  // 256
    int cnt = g_count[b];
    if (base >= cnt) return;

    if (t < 128) idx_s[t] = (base + t < cnt) ? g_list[b * NN + base + t] : -1;

    // load weights (8192 floats = 2048 float4, 8 per thread)
    const float4* Wg = (const float4*)(lin_w + l * 128 * 64);
    float4* Ws4 = (float4*)W_s;
#pragma unroll
    for (int i = 0; i < 8; i++) Ws4[t + i * 256] = Wg[t + i * 256];
    __syncthreads();

    // gather: 2 threads per row; h=0 -> x (k 0..63), h=1 -> agg (k 64..127)
    {
        int r = t & 127;
        int h = t >> 7;
        int idx = idx_s[r];
        if (idx >= 0) {
            const float* srcp = h ? (g_agg + (b * NN + idx) * DD)
                                  : (g_x + (b * NN + idx) * DD);
            const float4* s4 = (const float4*)srcp;
#pragma unroll
            for (int c = 0; c < 16; c++) {
                float4 v = s4[c];
                int k0 = h * 64 + c * 4;
                cat_s[(k0 + 0) * 128 + r] = v.x;
                cat_s[(k0 + 1) * 128 + r] = v.y;
                cat_s[(k0 + 2) * 128 + r] = v.z;
                cat_s[(k0 + 3) * 128 + r] = v.w;
            }
        } else {
#pragma unroll
            for (int c = 0; c < 64; c++) cat_s[(h * 64 + c) * 128 + r] = 0.f;
        }
    }
    __syncthreads();

    int tn = t >> 3;  // 32 row groups (4 rows each)
    int td = t & 7;   // 8 dim groups (8 dims each)
    float acc[4][8];
    {
        float4 b0 = *(const float4*)&lin_b[l * 64 + td * 8];
        float4 b1 = *(const float4*)&lin_b[l * 64 + td * 8 + 4];
        float bb[8] = {b0.x, b0.y, b0.z, b0.w, b1.x, b1.y, b1.z, b1.w};
#pragma unroll
        for (int i = 0; i < 4; i++)
#pragma unroll
            for (int j = 0; j < 8; j++) acc[i][j] = bb[j];
    }

#pragma unroll 4
    for (int k = 0; k < 128; ++k) {
        const float4 a4 = *(const float4*)(cat_s + k * 128 + tn * 4);
        const float4 w0 = *(const float4*)(W_s + k * 64 + td * 8);
        const float4 w1 = *(const float4*)(W_s + k * 64 + td * 8 + 4);
        float aa[4] = {a4.x, a4.y, a4.z, a4.w};
        float ww[8] = {w0.x, w0.y, w0.z, w0.w, w1.x, w1.y, w1.z, w1.w};
#pragma unroll
        for (int i = 0; i < 4; i++)
#pragma unroll
            for (int j = 0; j < 8; j++)
                acc[i][j] = fmaf(aa[i], ww[j], acc[i][j]);
    }

    // fused LayerNorm (+relu+shortcut); dims spread over 8 td lanes
    float lng[8], lnb[8];
    {
        float4 g0 = *(const float4*)&ln_g[l * 64 + td * 8];
        float4 g1 = *(const float4*)&ln_g[l * 64 + td * 8 + 4];
        float4 c0 = *(const float4*)&ln_b[l * 64 + td * 8];
        float4 c1 = *(const float4*)&ln_b[l * 64 + td * 8 + 4];
        lng[0] = g0.x; lng[1] = g0.y; lng[2] = g0.z; lng[3] = g0.w;
        lng[4] = g1.x; lng[5] = g1.y; lng[6] = g1.z; lng[7] = g1.w;
        lnb[0] = c0.x; lnb[1] = c0.y; lnb[2] = c0.z; lnb[3] = c0.w;
        lnb[4] = c1.x; lnb[5] = c1.y; lnb[6] = c1.z; lnb[7] = c1.w;
    }
#pragma unroll
    for (int i = 0; i < 4; i++) {
        float s = 0.f, s2 = 0.f;
#pragma unroll
        for (int j = 0; j < 8; j++) {
            s += acc[i][j];
            s2 += acc[i][j] * acc[i][j];
        }
#pragma unroll
        for (int m = 1; m < 8; m <<= 1) {
            s += __shfl_xor_sync(0xffffffffu, s, m);
            s2 += __shfl_xor_sync(0xffffffffu, s2, m);
        }
        float mu = s * (1.f / 64.f);
        float var = s2 * (1.f / 64.f) - mu * mu;
        float inv = rsqrtf(var + 1e-5f);
        int row = idx_s[tn * 4 + i];
        if (row >= 0) {
            float* xr = g_x + (b * NN + row) * DD + td * 8;
            float4 x0 = *(const float4*)xr;
            float4 x1 = *(const float4*)(xr + 4);
            float xo[8] = {x0.x, x0.y, x0.z, x0.w, x1.x, x1.y, x1.z, x1.w};
            float o[8];
#pragma unroll
            for (int j = 0; j < 8; j++)
                o[j] = fmaxf((acc[i][j] - mu) * inv * lng[j] + lnb[j], 0.f) +
                       xo[j];
            *(float4*)xr = make_float4(o[0], o[1], o[2], o[3]);
            *(float4*)(xr + 4) = make_float4(o[4], o[5], o[6], o[7]);
            float* agr = g_agg + (b * NN + row) * DD + td * 8;
            *(float4*)agr = make_float4(0.f, 0.f, 0.f, 0.f);
            *(float4*)(agr + 4) = make_float4(0.f, 0.f, 0.f, 0.f);
        }
    }
}

// ---------------------------------------------------------------------------
// final: out = relu([x ; query] @ mlp_w + mlp_b); query part precomputed.
// Block: 64 nodes, 256 threads, 4 nodes x 8 dims per thread. NN % 64 == 0.
// ---------------------------------------------------------------------------
__global__ void __launch_bounds__(256)
final_kernel(const float* __restrict__ mlp_w, float* __restrict__ out) {
    extern __shared__ float smem[];
    float* W_s = smem;             // [64][128] = 32KB
    float* x_s = smem + 64 * 128;  // [k][node] = 16KB
    int b = blockIdx.y;
    int n0 = blockIdx.x * 64;
    int t = threadIdx.x;

    const float4* Wg = (const float4*)mlp_w;  // first 64 rows = 2048 float4
    float4* Ws4 = (float4*)W_s;
#pragma unroll
    for (int i = 0; i < 8; i++) Ws4[t + i * 256] = Wg[t + i * 256];

    const float* xb = g_x + (b * NN + n0) * DD;
    int nl = t & 63;
    int c0 = t >> 6;
#pragma unroll
    for (int i = 0; i < 4; i++) {
        int cc = c0 + i * 4;
        float4 v = *(const float4*)&xb[nl * DD + cc * 4];
        x_s[(cc * 4 + 0) * 64 + nl] = v.x;
        x_s[(cc * 4 + 1) * 64 + nl] = v.y;
        x_s[(cc * 4 + 2) * 64 + nl] = v.z;
        x_s[(cc * 4 + 3) * 64 + nl] = v.w;
    }
    __syncthreads();

    int tn = t >> 4;  // 16 node groups (4 nodes each)
    int td = t & 15;  // 16 dim groups (8 dims each)
    float acc[4][8];
#pragma unroll
    for (int i = 0; i < 4; i++)
#pragma unroll
        for (int j = 0; j < 8; j++) acc[i][j] = 0.f;

#pragma unroll 4
    for (int k = 0; k < 64; ++k) {
        const float4 a4 = *(const float4*)(x_s + k * 64 + tn * 4);
        const float4 w0 = *(const float4*)(W_s + k * 128 + td * 8);
        const float4 w1 = *(const float4*)(W_s + k * 128 + td * 8 + 4);
        float aa[4] = {a4.x, a4.y, a4.z, a4.w};
        float ww[8] = {w0.x, w0.y, w0.z, w0.w, w1.x, w1.y, w1.z, w1.w};
#pragma unroll
        for (int i = 0; i < 4; i++)
#pragma unroll
            for (int j = 0; j < 8; j++)
                acc[i][j] = fmaf(aa[i], ww[j], acc[i][j]);
    }

    float qp[8];
    const float4 q0 = *(const float4*)&g_qpart[b * 128 + td * 8];
    const float4 q1 = *(const float4*)&g_qpart[b * 128 + td * 8 + 4];
    qp[0] = q0.x; qp[1] = q0.y; qp[2] = q0.z; qp[3] = q0.w;
    qp[4] = q1.x; qp[5] = q1.y; qp[6] = q1.z; qp[7] = q1.w;

#pragma unroll
    for (int i = 0; i < 4; i++) {
        int n = n0 + tn * 4 + i;
        float* op = out + ((long)(b * NN + n)) * 128 + td * 8;
        float4 o0, o1;
        o0.x = fmaxf(acc[i][0] + qp[0], 0.f);
        o0.y = fmaxf(acc[i][1] + qp[1], 0.f);
        o0.z = fmaxf(acc[i][2] + qp[2], 0.f);
        o0.w = fmaxf(acc[i][3] + qp[3], 0.f);
        o1.x = fmaxf(acc[i][4] + qp[4], 0.f);
        o1.y = fmaxf(acc[i][5] + qp[5], 0.f);
        o1.z = fmaxf(acc[i][6] + qp[6], 0.f);
        o1.w = fmaxf(acc[i][7] + qp[7], 0.f);
        *(float4*)op = o0;
        *(float4*)(op + 4) = o1;
    }
}

// ---------------------------------------------------------------------------
extern "C" void kernel_launch(void* const* d_in, const int* in_sizes, int n_in,
                              void* d_out, int out_size) {
    const float* rel_reps = (const float*)d_in[0];
    const int* h_index = (const int*)d_in[1];
    const int* r_index = (const int*)d_in[2];
    const int* edge_index = (const int*)d_in[3];
    const int* edge_type = (const int*)d_in[4];
    const float* pw1 = (const float*)d_in[5];
    const float* pb1 = (const float*)d_in[6];
    const float* pw2 = (const float*)d_in[7];
    const float* pb2 = (const float*)d_in[8];
    const float* lin_w = (const float*)d_in[9];
    const float* lin_b = (const float*)d_in[10];
    const float* ln_g = (const float*)d_in[11];
    const float* ln_b = (const float*)d_in[12];
    const float* mlp_w = (const float*)d_in[13];
    const float* mlp_b = (const float*)d_in[14];
    float* out = (float*)d_out;

    cudaFuncSetAttribute(linear_kernel,
                         cudaFuncAttributeMaxDynamicSharedMemorySize, 98304);
    cudaFuncSetAttribute(final_kernel,
                         cudaFuncAttributeMaxDynamicSharedMemorySize, 49152);

    prep_kernel<<<1, 256>>>(rel_reps, r_index, h_index, mlp_w, mlp_b, lin_b,
                            ln_g, ln_b);
    init_x<<<(BB * NN * DD / 4 + 255) / 256, 256>>>(h_index);
    for (int l = 0; l < LLAYERS; l++) {
        relproj_kernel<<<BB * RR, 64>>>(rel_reps, pw1, pb1, pw2, pb2, h_index,
                                        l);
        message_kernel<<<(BB * EE / 4 + 255) / 256, 256>>>(edge_index,
                                                           edge_type);
        linear_kernel<<<dim3((NN + 127) / 128, BB), 256, 98304>>>(
            lin_w, lin_b, ln_g, ln_b, l);
    }
    final_kernel<<<dim3(NN / 64, BB), 256, 49152>>>(mlp_w, out);
}

// round 7
// speedup vs baseline: 1.3676x; 1.3676x over previous
#include <cuda_runtime.h>

#define BB 2
#define NN 40000
#define EE 400000
#define RR 64
#define DD 64
#define LLAYERS 6
#define MASKW 1250  // (NN+31)/32

// Scratch (allocation-free rule: __device__ globals)
__device__ __align__(16) float g_x[BB * NN * DD];    // 20.5 MB
__device__ __align__(16) float g_agg[BB * NN * DD];  // 20.5 MB (invariant: list rows zero at entry of each gather)
__device__ __align__(16) float g_rel[BB * RR * DD];
__device__ __align__(16) float g_query[BB * DD];
__device__ __align__(16) float g_qpart[BB * 2 * DD];
__device__ unsigned g_mask[BB * MASKW];  // bit set => x row may be nonzero
__device__ int g_list[BB * NN];
__device__ int g_count[BB];
__device__ int g_dense;  // 1 => zero rows would produce nonzero output
// CSR by dst (shared by both batches — same graph)
__device__ int g_cnt[NN];
__device__ int g_fill[NN];
__device__ int g_csr_ptr[NN + 1];
__device__ int g_csr_eid[EE];

// ---------------------------------------------------------------------------
// prep
// ---------------------------------------------------------------------------
__global__ void prep_kernel(const float* __restrict__ rel_reps,
                            const int* __restrict__ r_index,
                            const int* __restrict__ h_index,
                            const float* __restrict__ mlp_w,
                            const float* __restrict__ mlp_b,
                            const float* __restrict__ lin_b,
                            const float* __restrict__ ln_g,
                            const float* __restrict__ ln_b) {
    __shared__ float q_s[BB * DD];
    int t = threadIdx.x;  // 256
    for (int i = t; i < BB * MASKW; i += 256) g_mask[i] = 0u;
    if (t < BB * DD) {
        int b = t / DD, d = t % DD;
        float v = rel_reps[(b * RR + r_index[b]) * DD + d];
        g_query[t] = v;
        q_s[t] = v;
    }
    __syncthreads();
    if (t < BB) {
        int h = h_index[t];
        g_mask[t * MASKW + (h >> 5)] = 1u << (h & 31);
    }
    if (t == 0) {
        int dense = 0;
        for (int l = 0; l < LLAYERS; l++) {
            const float* lb = lin_b + l * DD;
            float mu = 0.f;
            for (int d = 0; d < DD; d++) mu += lb[d];
            mu *= (1.f / DD);
            float var = 0.f;
            for (int d = 0; d < DD; d++) {
                float dv = lb[d] - mu;
                var += dv * dv;
            }
            var *= (1.f / DD);
            float inv = rsqrtf(var + 1e-5f);
            for (int d = 0; d < DD; d++) {
                float o = (lb[d] - mu) * inv * ln_g[l * DD + d] + ln_b[l * DD + d];
                if (o > 0.f) dense = 1;
            }
        }
        g_dense = dense;
    }
    int b = t / 128, e = t % 128;
    float acc = mlp_b[e];
#pragma unroll
    for (int k = 0; k < DD; k++)
        acc = fmaf(q_s[b * DD + k], mlp_w[(DD + k) * 128 + e], acc);
    g_qpart[b * 128 + e] = acc;
}

// ---------------------------------------------------------------------------
// CSR build (once per launch; replay-safe)
// ---------------------------------------------------------------------------
__global__ void csr_clear() {
    int n = blockIdx.x * 256 + threadIdx.x;
    if (n < NN) g_cnt[n] = 0;
}
__global__ void csr_hist(const int* __restrict__ edge_index) {
    int e = blockIdx.x * 256 + threadIdx.x;
    if (e < EE) atomicAdd(&g_cnt[__ldg(&edge_index[EE + e])], 1);
}
__global__ void csr_scan() {  // single block, 1024 threads, chunk=40 bins
    __shared__ int part[1024];
    int t = threadIdx.x;
    int lo = t * 40;
    int hi = lo + 40 < NN ? lo + 40 : NN;
    int s = 0;
    for (int i = lo; i < hi; i++) s += g_cnt[i];
    part[t] = s;
    __syncthreads();
    for (int off = 1; off < 1024; off <<= 1) {
        int v = (t >= off) ? part[t - off] : 0;
        __syncthreads();
        part[t] += v;
        __syncthreads();
    }
    int base = part[t] - s;  // exclusive prefix
    for (int i = lo; i < hi; i++) {
        g_csr_ptr[i] = base;
        g_fill[i] = base;
        base += g_cnt[i];
    }
    if (t == 1023) g_csr_ptr[NN] = EE;
}
__global__ void csr_scatter(const int* __restrict__ edge_index) {
    int e = blockIdx.x * 256 + threadIdx.x;
    if (e >= EE) return;
    int pos = atomicAdd(&g_fill[__ldg(&edge_index[EE + e])], 1);
    g_csr_eid[pos] = e;
}

// ---------------------------------------------------------------------------
// init x: zeros everywhere, query at h_index[b]
// ---------------------------------------------------------------------------
__global__ void init_x(const int* __restrict__ h_index) {
    int gid = blockIdx.x * 256 + threadIdx.x;
    const int per_b = NN * DD / 4;
    if (gid >= BB * per_b) return;
    int b = gid / per_b;
    int r = gid - b * per_b;
    int n = r >> 4;
    int d4 = r & 15;
    float4 v = make_float4(0.f, 0.f, 0.f, 0.f);
    if (n == __ldg(&h_index[b]))
        v = *(const float4*)&g_query[b * DD + d4 * 4];
    ((float4*)g_x)[gid] = v;
}

// ---------------------------------------------------------------------------
// per-layer relation projection + count reset
// ---------------------------------------------------------------------------
__global__ void relproj_kernel(const float* __restrict__ rel_reps,
                               const float* __restrict__ pw1,
                               const float* __restrict__ pb1,
                               const float* __restrict__ pw2,
                               const float* __restrict__ pb2, int l) {
    int br = blockIdx.x;
    int b = br >> 6;
    int e = threadIdx.x;  // 64
    __shared__ float in_s[DD];
    __shared__ float hid_s[DD];
    in_s[e] = rel_reps[br * DD + e];
    __syncthreads();
    const float* W1 = pw1 + l * DD * DD;
    float acc = pb1[l * DD + e];
#pragma unroll 16
    for (int k = 0; k < DD; k++) acc = fmaf(in_s[k], W1[k * DD + e], acc);
    hid_s[e] = fmaxf(acc, 0.f);
    __syncthreads();
    const float* W2 = pw2 + l * DD * DD;
    float acc2 = pb2[l * DD + e];
#pragma unroll 16
    for (int k = 0; k < DD; k++) acc2 = fmaf(hid_s[k], W2[k * DD + e], acc2);
    g_rel[br * DD + e] = acc2;

    if ((br & 63) == 0 && e == 0) g_count[b] = 0;
}

// ---------------------------------------------------------------------------
// gather message: warp per (b,dst). Lanes probe 32 edges' src masks in
// parallel; active edges accumulate x[src]*rel[type] as float2/lane.
// No atomics on agg. Boundary query added at dst==h. Touched dsts marked.
// Races that early-mark a node read x rows that are provably zero => exact.
// ---------------------------------------------------------------------------
__global__ void __launch_bounds__(256)
gather_kernel(const int* __restrict__ edge_index,
              const int* __restrict__ edge_type,
              const int* __restrict__ h_index) {
    const unsigned FULL = 0xffffffffu;
    int w = blockIdx.x * 8 + (threadIdx.x >> 5);  // grid covers BB*NN exactly
    int lane = threadIdx.x & 31;
    int b = (w >= NN) ? 1 : 0;
    int dst = w - b * NN;
    const unsigned* mask = g_mask + b * MASKW;
    int beg = __ldg(&g_csr_ptr[dst]);
    int end = __ldg(&g_csr_ptr[dst + 1]);
    int h = __ldg(&h_index[b]);
    float2 acc = make_float2(0.f, 0.f);
    bool any = false;
    for (int base = beg; base < end; base += 32) {
        int i = base + lane;
        int eid = 0, src = 0, ty = 0;
        bool a = false;
        if (i < end) {
            eid = __ldg(&g_csr_eid[i]);
            src = __ldg(&edge_index[eid]);
            a = (mask[src >> 5] >> (src & 31)) & 1u;
        }
        unsigned ball = __ballot_sync(FULL, a);
        if (a) ty = __ldg(&edge_type[eid]);
        any |= (ball != 0);
        while (ball) {
            int l = __ffs(ball) - 1;
            ball &= ball - 1;
            int s = __shfl_sync(FULL, src, l);
            int tt = __shfl_sync(FULL, ty, l);
            float2 xv = *(const float2*)&g_x[(b * NN + s) * DD + lane * 2];
            float2 rv = *(const float2*)&g_rel[(b * RR + tt) * DD + lane * 2];
            acc.x = fmaf(xv.x, rv.x, acc.x);
            acc.y = fmaf(xv.y, rv.y, acc.y);
        }
    }
    if (dst == h) {
        float2 q = *(const float2*)&g_query[b * DD + lane * 2];
        acc.x += q.x;
        acc.y += q.y;
        any = true;
    }
    if (any) {
        *(float2*)&g_agg[(b * NN + dst) * DD + lane * 2] = acc;
        if (lane == 0) {
            unsigned bit = 1u << (dst & 31);
            if (!(mask[dst >> 5] & bit))
                atomicOr(&g_mask[b * MASKW + (dst >> 5)], bit);
        }
    }
}

// ---------------------------------------------------------------------------
// compact: mask -> list, warp-aggregated, order-preserving within warp.
// ---------------------------------------------------------------------------
__global__ void compact_kernel() {
    int gid = blockIdx.x * 256 + threadIdx.x;
    if (gid >= BB * NN) return;
    int b = gid / NN;
    int n = gid - b * NN;
    bool act;
    if (g_dense) {
        act = true;
        if ((n & 31) == 0) g_mask[b * MASKW + (n >> 5)] = 0xffffffffu;
    } else {
        act = (g_mask[b * MASKW + (n >> 5)] >> (n & 31)) & 1u;
    }
    unsigned bal = __ballot_sync(0xffffffffu, act);
    if (!bal) return;
    int lane = threadIdx.x & 31;
    int pos = 0;
    if (lane == 0) pos = atomicAdd(&g_count[b], __popc(bal));
    pos = __shfl_sync(0xffffffffu, pos, 0);
    if (act)
        g_list[b * NN + pos + __popc(bal & ((1u << lane) - 1u))] = n;
}

// ---------------------------------------------------------------------------
// fused linear (R3-proven shape): 64 list rows, 256 threads, 4x4 tile.
// x = relu(LN(cat(x,agg)@W + b)) + x; agg row -> 0 after use.
// ---------------------------------------------------------------------------
__global__ void linear_kernel(const float* __restrict__ lin_w,
                              const float* __restrict__ lin_b,
                              const float* __restrict__ ln_g,
                              const float* __restrict__ ln_b, int l) {
    extern __shared__ float smem[];
    float* W_s = smem;               // [128][64] = 32KB
    float* cat_s = smem + 128 * 64;  // [k][node] transposed = 32KB
    __shared__ int idx_s[64];
    int b = blockIdx.y;
    int base = blockIdx.x * 64;
    int t = threadIdx.x;  // 256
    int cnt = g_count[b];
    if (base >= cnt) return;

    if (t < 64) idx_s[t] = (base + t < cnt) ? g_list[b * NN + base + t] : -1;

    const float4* Wg = (const float4*)(lin_w + l * 128 * 64);
    float4* Ws4 = (float4*)W_s;
#pragma unroll
    for (int i = 0; i < 8; i++) Ws4[t + i * 256] = Wg[t + i * 256];
    __syncthreads();

    int nl = t & 63;
    int c0 = t >> 6;  // 0..3
    int idx = idx_s[nl];
    const float* xb = g_x + (b * NN + idx) * DD;
    const float* ab = g_agg + (b * NN + idx) * DD;
#pragma unroll
    for (int i = 0; i < 4; i++) {
        int cc = c0 + i * 4;  // float4 col 0..15
        float4 v = make_float4(0.f, 0.f, 0.f, 0.f);
        float4 a = make_float4(0.f, 0.f, 0.f, 0.f);
        if (idx >= 0) {
            v = *(const float4*)&xb[cc * 4];
            a = *(const float4*)&ab[cc * 4];
        }
        cat_s[(cc * 4 + 0) * 64 + nl] = v.x;
        cat_s[(cc * 4 + 1) * 64 + nl] = v.y;
        cat_s[(cc * 4 + 2) * 64 + nl] = v.z;
        cat_s[(cc * 4 + 3) * 64 + nl] = v.w;
        cat_s[(64 + cc * 4 + 0) * 64 + nl] = a.x;
        cat_s[(64 + cc * 4 + 1) * 64 + nl] = a.y;
        cat_s[(64 + cc * 4 + 2) * 64 + nl] = a.z;
        cat_s[(64 + cc * 4 + 3) * 64 + nl] = a.w;
    }
    __syncthreads();

    int tn = t >> 4;  // node group (4 nodes)
    int td = t & 15;  // dim group  (4 dims)
    float4 bias4 = *(const float4*)&lin_b[l * 64 + td * 4];
    float acc[4][4];
#pragma unroll
    for (int i = 0; i < 4; i++) {
        acc[i][0] = bias4.x; acc[i][1] = bias4.y;
        acc[i][2] = bias4.z; acc[i][3] = bias4.w;
    }

#pragma unroll 4
    for (int k = 0; k < 128; ++k) {
        const float4 a4 = *(const float4*)(cat_s + k * 64 + tn * 4);
        const float4 w4 = *(const float4*)(W_s + k * 64 + td * 4);
        float aa[4] = {a4.x, a4.y, a4.z, a4.w};
        float ww[4] = {w4.x, w4.y, w4.z, w4.w};
#pragma unroll
        for (int i = 0; i < 4; i++)
#pragma unroll
            for (int j = 0; j < 4; j++)
                acc[i][j] = fmaf(aa[i], ww[j], acc[i][j]);
    }

    float4 g4 = *(const float4*)&ln_g[l * 64 + td * 4];
    float4 bb4 = *(const float4*)&ln_b[l * 64 + td * 4];
    float lng[4] = {g4.x, g4.y, g4.z, g4.w};
    float lnb[4] = {bb4.x, bb4.y, bb4.z, bb4.w};
#pragma unroll
    for (int i = 0; i < 4; i++) {
        float s = acc[i][0] + acc[i][1] + acc[i][2] + acc[i][3];
        float s2 = acc[i][0] * acc[i][0] + acc[i][1] * acc[i][1] +
                   acc[i][2] * acc[i][2] + acc[i][3] * acc[i][3];
#pragma unroll
        for (int m = 1; m < 16; m <<= 1) {
            s += __shfl_xor_sync(0xffffffffu, s, m);
            s2 += __shfl_xor_sync(0xffffffffu, s2, m);
        }
        float mu = s * (1.f / 64.f);
        float var = s2 * (1.f / 64.f) - mu * mu;
        float inv = rsqrtf(var + 1e-5f);
        int row = idx_s[tn * 4 + i];
        if (row >= 0) {
            float* xr = g_x + (b * NN + row) * DD + td * 4;
            float4 xold = *(const float4*)xr;
            float4 o;
            o.x = fmaxf((acc[i][0] - mu) * inv * lng[0] + lnb[0], 0.f) + xold.x;
            o.y = fmaxf((acc[i][1] - mu) * inv * lng[1] + lnb[1], 0.f) + xold.y;
            o.z = fmaxf((acc[i][2] - mu) * inv * lng[2] + lnb[2], 0.f) + xold.z;
            o.w = fmaxf((acc[i][3] - mu) * inv * lng[3] + lnb[3], 0.f) + xold.w;
            *(float4*)xr = o;
            *(float4*)(g_agg + (b * NN + row) * DD + td * 4) =
                make_float4(0.f, 0.f, 0.f, 0.f);
        }
    }
}

// ---------------------------------------------------------------------------
// final: out = relu([x ; query] @ mlp_w + mlp_b); query part precomputed.
// ---------------------------------------------------------------------------
__global__ void final_kernel(const float* __restrict__ mlp_w,
                             float* __restrict__ out) {
    extern __shared__ float smem[];
    float* W_s = smem;             // [64][128] = 32KB
    float* x_s = smem + 64 * 128;  // [k][node] = 16KB
    int b = blockIdx.y;
    int n0 = blockIdx.x * 64;
    int t = threadIdx.x;

    const float4* Wg = (const float4*)mlp_w;
    float4* Ws4 = (float4*)W_s;
#pragma unroll
    for (int i = 0; i < 8; i++) Ws4[t + i * 256] = Wg[t + i * 256];

    const float* xb = g_x + (b * NN + n0) * DD;
    int nl = t & 63;
    int c0 = t >> 6;
#pragma unroll
    for (int i = 0; i < 4; i++) {
        int cc = c0 + i * 4;
        float4 v = *(const float4*)&xb[nl * DD + cc * 4];
        x_s[(cc * 4 + 0) * 64 + nl] = v.x;
        x_s[(cc * 4 + 1) * 64 + nl] = v.y;
        x_s[(cc * 4 + 2) * 64 + nl] = v.z;
        x_s[(cc * 4 + 3) * 64 + nl] = v.w;
    }
    __syncthreads();

    int tn = t >> 4;  // 16 node groups (4 nodes each)
    int td = t & 15;  // 16 dim groups (8 dims each)
    float acc[4][8];
#pragma unroll
    for (int i = 0; i < 4; i++)
#pragma unroll
        for (int j = 0; j < 8; j++) acc[i][j] = 0.f;

#pragma unroll 4
    for (int k = 0; k < 64; ++k) {
        const float4 a4 = *(const float4*)(x_s + k * 64 + tn * 4);
        const float4 w0 = *(const float4*)(W_s + k * 128 + td * 8);
        const float4 w1 = *(const float4*)(W_s + k * 128 + td * 8 + 4);
        float aa[4] = {a4.x, a4.y, a4.z, a4.w};
        float ww[8] = {w0.x, w0.y, w0.z, w0.w, w1.x, w1.y, w1.z, w1.w};
#pragma unroll
        for (int i = 0; i < 4; i++)
#pragma unroll
            for (int j = 0; j < 8; j++)
                acc[i][j] = fmaf(aa[i], ww[j], acc[i][j]);
    }

    float qp[8];
    const float4 q0 = *(const float4*)&g_qpart[b * 128 + td * 8];
    const float4 q1 = *(const float4*)&g_qpart[b * 128 + td * 8 + 4];
    qp[0] = q0.x; qp[1] = q0.y; qp[2] = q0.z; qp[3] = q0.w;
    qp[4] = q1.x; qp[5] = q1.y; qp[6] = q1.z; qp[7] = q1.w;

#pragma unroll
    for (int i = 0; i < 4; i++) {
        int n = n0 + tn * 4 + i;
        float* op = out + ((long)(b * NN + n)) * 128 + td * 8;
        float4 o0, o1;
        o0.x = fmaxf(acc[i][0] + qp[0], 0.f);
        o0.y = fmaxf(acc[i][1] + qp[1], 0.f);
        o0.z = fmaxf(acc[i][2] + qp[2], 0.f);
        o0.w = fmaxf(acc[i][3] + qp[3], 0.f);
        o1.x = fmaxf(acc[i][4] + qp[4], 0.f);
        o1.y = fmaxf(acc[i][5] + qp[5], 0.f);
        o1.z = fmaxf(acc[i][6] + qp[6], 0.f);
        o1.w = fmaxf(acc[i][7] + qp[7], 0.f);
        *(float4*)op = o0;
        *(float4*)(op + 4) = o1;
    }
}

// ---------------------------------------------------------------------------
extern "C" void kernel_launch(void* const* d_in, const int* in_sizes, int n_in,
                              void* d_out, int out_size) {
    const float* rel_reps = (const float*)d_in[0];
    const int* h_index = (const int*)d_in[1];
    const int* r_index = (const int*)d_in[2];
    const int* edge_index = (const int*)d_in[3];
    const int* edge_type = (const int*)d_in[4];
    const float* pw1 = (const float*)d_in[5];
    const float* pb1 = (const float*)d_in[6];
    const float* pw2 = (const float*)d_in[7];
    const float* pb2 = (const float*)d_in[8];
    const float* lin_w = (const float*)d_in[9];
    const float* lin_b = (const float*)d_in[10];
    const float* ln_g = (const float*)d_in[11];
    const float* ln_b = (const float*)d_in[12];
    const float* mlp_w = (const float*)d_in[13];
    const float* mlp_b = (const float*)d_in[14];
    float* out = (float*)d_out;

    cudaFuncSetAttribute(linear_kernel,
                         cudaFuncAttributeMaxDynamicSharedMemorySize, 65536);
    cudaFuncSetAttribute(final_kernel,
                         cudaFuncAttributeMaxDynamicSharedMemorySize, 49152);

    prep_kernel<<<1, 256>>>(rel_reps, r_index, h_index, mlp_w, mlp_b, lin_b,
                            ln_g, ln_b);
    csr_clear<<<(NN + 255) / 256, 256>>>();
    csr_hist<<<(EE + 255) / 256, 256>>>(edge_index);
    csr_scan<<<1, 1024>>>();
    csr_scatter<<<(EE + 255) / 256, 256>>>(edge_index);
    init_x<<<(BB * NN * DD / 4 + 255) / 256, 256>>>(h_index);
    for (int l = 0; l < LLAYERS; l++) {
        relproj_kernel<<<BB * RR, 64>>>(rel_reps, pw1, pb1, pw2, pb2, l);
        gather_kernel<<<BB * NN / 8, 256>>>(edge_index, edge_type, h_index);
        compact_kernel<<<(BB * NN + 255) / 256, 256>>>();
        linear_kernel<<<dim3((NN + 63) / 64, BB), 256, 65536>>>(lin_w, lin_b,
                                                                ln_g, ln_b, l);
    }
    final_kernel<<<dim3(NN / 64, BB), 256, 49152>>>(mlp_w, out);
}

// round 8
// speedup vs baseline: 1.5466x; 1.1309x over previous
#include <cuda_runtime.h>

#define BB 2
#define NN 40000
#define EE 400000
#define RR 64
#define DD 64
#define LLAYERS 6
#define MASKW 1250   // (NN+31)/32
#define SCANB 157    // (NN+255)/256

// Scratch (allocation-free rule: __device__ globals)
__device__ __align__(16) float g_x[BB * NN * DD];    // 20.5 MB
__device__ __align__(16) float g_agg[BB * NN * DD];  // 20.5 MB (invariant: list rows zero at entry of each gather)
__device__ __align__(16) float g_rel[BB * RR * DD];
__device__ __align__(16) float g_query[BB * DD];
__device__ __align__(16) float g_qpart[BB * 2 * DD];
__device__ unsigned g_mask[BB * MASKW];  // bit set => x row may be nonzero
__device__ int g_list[BB * NN];
__device__ int g_count[BB];
__device__ int g_dense;  // 1 => zero rows would produce nonzero output
// CSR by dst (shared by both batches — same graph)
__device__ int g_cnt[NN];
__device__ int g_fill[NN];
__device__ int g_csr_ptr[NN + 1];
__device__ int g_csr_eid[EE];
__device__ int g_bsum[SCANB + 3];

// ---------------------------------------------------------------------------
// prep
// ---------------------------------------------------------------------------
__global__ void prep_kernel(const float* __restrict__ rel_reps,
                            const int* __restrict__ r_index,
                            const int* __restrict__ h_index,
                            const float* __restrict__ mlp_w,
                            const float* __restrict__ mlp_b,
                            const float* __restrict__ lin_b,
                            const float* __restrict__ ln_g,
                            const float* __restrict__ ln_b) {
    __shared__ float q_s[BB * DD];
    int t = threadIdx.x;  // 256
    for (int i = t; i < BB * MASKW; i += 256) g_mask[i] = 0u;
    if (t < BB * DD) {
        int b = t / DD, d = t % DD;
        float v = rel_reps[(b * RR + r_index[b]) * DD + d];
        g_query[t] = v;
        q_s[t] = v;
    }
    __syncthreads();
    if (t < BB) {
        int h = h_index[t];
        g_mask[t * MASKW + (h >> 5)] = 1u << (h & 31);
    }
    if (t == 0) {
        int dense = 0;
        for (int l = 0; l < LLAYERS; l++) {
            const float* lb = lin_b + l * DD;
            float mu = 0.f;
            for (int d = 0; d < DD; d++) mu += lb[d];
            mu *= (1.f / DD);
            float var = 0.f;
            for (int d = 0; d < DD; d++) {
                float dv = lb[d] - mu;
                var += dv * dv;
            }
            var *= (1.f / DD);
            float inv = rsqrtf(var + 1e-5f);
            for (int d = 0; d < DD; d++) {
                float o = (lb[d] - mu) * inv * ln_g[l * DD + d] + ln_b[l * DD + d];
                if (o > 0.f) dense = 1;
            }
        }
        g_dense = dense;
    }
    int b = t / 128, e = t % 128;
    float acc = mlp_b[e];
#pragma unroll
    for (int k = 0; k < DD; k++)
        acc = fmaf(q_s[b * DD + k], mlp_w[(DD + k) * 128 + e], acc);
    g_qpart[b * 128 + e] = acc;
}

// ---------------------------------------------------------------------------
// CSR build (once per launch; replay-safe). Multi-block 3-stage scan.
// ---------------------------------------------------------------------------
__global__ void csr_clear() {
    int n = blockIdx.x * 256 + threadIdx.x;
    if (n < NN) g_cnt[n] = 0;
}
__global__ void csr_hist(const int* __restrict__ edge_index) {
    int e = blockIdx.x * 256 + threadIdx.x;
    if (e < EE) atomicAdd(&g_cnt[__ldg(&edge_index[EE + e])], 1);
}
// stage 1: block-local scan; g_csr_ptr[i] = within-block exclusive prefix
__global__ void csr_scan1() {
    __shared__ int sh[256];
    int t = threadIdx.x;
    int i = blockIdx.x * 256 + t;
    int v = (i < NN) ? g_cnt[i] : 0;
    sh[t] = v;
    __syncthreads();
#pragma unroll
    for (int off = 1; off < 256; off <<= 1) {
        int u = (t >= off) ? sh[t - off] : 0;
        __syncthreads();
        sh[t] += u;
        __syncthreads();
    }
    if (t == 255) g_bsum[blockIdx.x] = sh[255];
    if (i < NN) g_csr_ptr[i] = sh[t] - v;
}
// stage 2: exclusive scan of block totals (1 block)
__global__ void csr_scan2() {
    __shared__ int sh[256];
    int t = threadIdx.x;
    int v = (t < SCANB) ? g_bsum[t] : 0;
    sh[t] = v;
    __syncthreads();
#pragma unroll
    for (int off = 1; off < 256; off <<= 1) {
        int u = (t >= off) ? sh[t - off] : 0;
        __syncthreads();
        sh[t] += u;
        __syncthreads();
    }
    if (t < SCANB) g_bsum[t] = sh[t] - v;
}
// stage 3: add block offsets, produce ptr + fill
__global__ void csr_scan3() {
    int i = blockIdx.x * 256 + threadIdx.x;
    if (i < NN) {
        int p = g_csr_ptr[i] + g_bsum[blockIdx.x];
        g_csr_ptr[i] = p;
        g_fill[i] = p;
    }
    if (i == 0) g_csr_ptr[NN] = EE;
}
__global__ void csr_scatter(const int* __restrict__ edge_index) {
    int e = blockIdx.x * 256 + threadIdx.x;
    if (e >= EE) return;
    int pos = atomicAdd(&g_fill[__ldg(&edge_index[EE + e])], 1);
    g_csr_eid[pos] = e;
}

// ---------------------------------------------------------------------------
// init x: zeros everywhere, query at h_index[b]
// ---------------------------------------------------------------------------
__global__ void init_x(const int* __restrict__ h_index) {
    int gid = blockIdx.x * 256 + threadIdx.x;
    const int per_b = NN * DD / 4;
    if (gid >= BB * per_b) return;
    int b = gid / per_b;
    int r = gid - b * per_b;
    int n = r >> 4;
    int d4 = r & 15;
    float4 v = make_float4(0.f, 0.f, 0.f, 0.f);
    if (n == __ldg(&h_index[b]))
        v = *(const float4*)&g_query[b * DD + d4 * 4];
    ((float4*)g_x)[gid] = v;
}

// ---------------------------------------------------------------------------
// per-layer relation projection + count reset
// ---------------------------------------------------------------------------
__global__ void relproj_kernel(const float* __restrict__ rel_reps,
                               const float* __restrict__ pw1,
                               const float* __restrict__ pb1,
                               const float* __restrict__ pw2,
                               const float* __restrict__ pb2, int l) {
    int br = blockIdx.x;
    int b = br >> 6;
    int e = threadIdx.x;  // 64
    __shared__ float in_s[DD];
    __shared__ float hid_s[DD];
    in_s[e] = rel_reps[br * DD + e];
    __syncthreads();
    const float* W1 = pw1 + l * DD * DD;
    float acc = pb1[l * DD + e];
#pragma unroll 16
    for (int k = 0; k < DD; k++) acc = fmaf(in_s[k], W1[k * DD + e], acc);
    hid_s[e] = fmaxf(acc, 0.f);
    __syncthreads();
    const float* W2 = pw2 + l * DD * DD;
    float acc2 = pb2[l * DD + e];
#pragma unroll 16
    for (int k = 0; k < DD; k++) acc2 = fmaf(hid_s[k], W2[k * DD + e], acc2);
    g_rel[br * DD + e] = acc2;

    if ((br & 63) == 0 && e == 0) g_count[b] = 0;
}

// ---------------------------------------------------------------------------
// gather message: warp per (b,dst). Lanes probe 32 edges' src masks in
// parallel; active edges accumulate x[src]*rel[type] as float2/lane.
// ---------------------------------------------------------------------------
__global__ void __launch_bounds__(256)
gather_kernel(const int* __restrict__ edge_index,
              const int* __restrict__ edge_type,
              const int* __restrict__ h_index) {
    const unsigned FULL = 0xffffffffu;
    int w = blockIdx.x * 8 + (threadIdx.x >> 5);  // grid covers BB*NN exactly
    int lane = threadIdx.x & 31;
    int b = (w >= NN) ? 1 : 0;
    int dst = w - b * NN;
    const unsigned* mask = g_mask + b * MASKW;
    int beg = __ldg(&g_csr_ptr[dst]);
    int end = __ldg(&g_csr_ptr[dst + 1]);
    int h = __ldg(&h_index[b]);
    float2 acc = make_float2(0.f, 0.f);
    bool any = false;
    for (int base = beg; base < end; base += 32) {
        int i = base + lane;
        int eid = 0, src = 0, ty = 0;
        bool a = false;
        if (i < end) {
            eid = __ldg(&g_csr_eid[i]);
            src = __ldg(&edge_index[eid]);
            a = (mask[src >> 5] >> (src & 31)) & 1u;
        }
        unsigned ball = __ballot_sync(FULL, a);
        if (a) ty = __ldg(&edge_type[eid]);
        any |= (ball != 0);
        while (ball) {
            int l = __ffs(ball) - 1;
            ball &= ball - 1;
            int s = __shfl_sync(FULL, src, l);
            int tt = __shfl_sync(FULL, ty, l);
            float2 xv = *(const float2*)&g_x[(b * NN + s) * DD + lane * 2];
            float2 rv = *(const float2*)&g_rel[(b * RR + tt) * DD + lane * 2];
            acc.x = fmaf(xv.x, rv.x, acc.x);
            acc.y = fmaf(xv.y, rv.y, acc.y);
        }
    }
    if (dst == h) {
        float2 q = *(const float2*)&g_query[b * DD + lane * 2];
        acc.x += q.x;
        acc.y += q.y;
        any = true;
    }
    if (any) {
        *(float2*)&g_agg[(b * NN + dst) * DD + lane * 2] = acc;
        if (lane == 0) {
            unsigned bit = 1u << (dst & 31);
            if (!(mask[dst >> 5] & bit))
                atomicOr(&g_mask[b * MASKW + (dst >> 5)], bit);
        }
    }
}

// ---------------------------------------------------------------------------
// compact: mask -> list, warp-aggregated, order-preserving within warp.
// ---------------------------------------------------------------------------
__global__ void compact_kernel() {
    int gid = blockIdx.x * 256 + threadIdx.x;
    if (gid >= BB * NN) return;
    int b = gid / NN;
    int n = gid - b * NN;
    bool act;
    if (g_dense) {
        act = true;
        if ((n & 31) == 0) g_mask[b * MASKW + (n >> 5)] = 0xffffffffu;
    } else {
        act = (g_mask[b * MASKW + (n >> 5)] >> (n & 31)) & 1u;
    }
    unsigned bal = __ballot_sync(0xffffffffu, act);
    if (!bal) return;
    int lane = threadIdx.x & 31;
    int pos = 0;
    if (lane == 0) pos = atomicAdd(&g_count[b], __popc(bal));
    pos = __shfl_sync(0xffffffffu, pos, 0);
    if (act)
        g_list[b * NN + pos + __popc(bal & ((1u << lane) - 1u))] = n;
}

// ---------------------------------------------------------------------------
// fused linear (R3-proven shape): 64 list rows, 256 threads, 4x4 tile.
// ---------------------------------------------------------------------------
__global__ void linear_kernel(const float* __restrict__ lin_w,
                              const float* __restrict__ lin_b,
                              const float* __restrict__ ln_g,
                              const float* __restrict__ ln_b, int l) {
    extern __shared__ float smem[];
    float* W_s = smem;               // [128][64] = 32KB
    float* cat_s = smem + 128 * 64;  // [k][node] transposed = 32KB
    __shared__ int idx_s[64];
    int b = blockIdx.y;
    int base = blockIdx.x * 64;
    int t = threadIdx.x;  // 256
    int cnt = g_count[b];
    if (base >= cnt) return;

    if (t < 64) idx_s[t] = (base + t < cnt) ? g_list[b * NN + base + t] : -1;

    const float4* Wg = (const float4*)(lin_w + l * 128 * 64);
    float4* Ws4 = (float4*)W_s;
#pragma unroll
    for (int i = 0; i < 8; i++) Ws4[t + i * 256] = Wg[t + i * 256];
    __syncthreads();

    int nl = t & 63;
    int c0 = t >> 6;  // 0..3
    int idx = idx_s[nl];
    const float* xb = g_x + (b * NN + idx) * DD;
    const float* ab = g_agg + (b * NN + idx) * DD;
#pragma unroll
    for (int i = 0; i < 4; i++) {
        int cc = c0 + i * 4;  // float4 col 0..15
        float4 v = make_float4(0.f, 0.f, 0.f, 0.f);
        float4 a = make_float4(0.f, 0.f, 0.f, 0.f);
        if (idx >= 0) {
            v = *(const float4*)&xb[cc * 4];
            a = *(const float4*)&ab[cc * 4];
        }
        cat_s[(cc * 4 + 0) * 64 + nl] = v.x;
        cat_s[(cc * 4 + 1) * 64 + nl] = v.y;
        cat_s[(cc * 4 + 2) * 64 + nl] = v.z;
        cat_s[(cc * 4 + 3) * 64 + nl] = v.w;
        cat_s[(64 + cc * 4 + 0) * 64 + nl] = a.x;
        cat_s[(64 + cc * 4 + 1) * 64 + nl] = a.y;
        cat_s[(64 + cc * 4 + 2) * 64 + nl] = a.z;
        cat_s[(64 + cc * 4 + 3) * 64 + nl] = a.w;
    }
    __syncthreads();

    int tn = t >> 4;  // node group (4 nodes)
    int td = t & 15;  // dim group  (4 dims)
    float4 bias4 = *(const float4*)&lin_b[l * 64 + td * 4];
    float acc[4][4];
#pragma unroll
    for (int i = 0; i < 4; i++) {
        acc[i][0] = bias4.x; acc[i][1] = bias4.y;
        acc[i][2] = bias4.z; acc[i][3] = bias4.w;
    }

#pragma unroll 4
    for (int k = 0; k < 128; ++k) {
        const float4 a4 = *(const float4*)(cat_s + k * 64 + tn * 4);
        const float4 w4 = *(const float4*)(W_s + k * 64 + td * 4);
        float aa[4] = {a4.x, a4.y, a4.z, a4.w};
        float ww[4] = {w4.x, w4.y, w4.z, w4.w};
#pragma unroll
        for (int i = 0; i < 4; i++)
#pragma unroll
            for (int j = 0; j < 4; j++)
                acc[i][j] = fmaf(aa[i], ww[j], acc[i][j]);
    }

    float4 g4 = *(const float4*)&ln_g[l * 64 + td * 4];
    float4 bb4 = *(const float4*)&ln_b[l * 64 + td * 4];
    float lng[4] = {g4.x, g4.y, g4.z, g4.w};
    float lnb[4] = {bb4.x, bb4.y, bb4.z, bb4.w};
#pragma unroll
    for (int i = 0; i < 4; i++) {
        float s = acc[i][0] + acc[i][1] + acc[i][2] + acc[i][3];
        float s2 = acc[i][0] * acc[i][0] + acc[i][1] * acc[i][1] +
                   acc[i][2] * acc[i][2] + acc[i][3] * acc[i][3];
#pragma unroll
        for (int m = 1; m < 16; m <<= 1) {
            s += __shfl_xor_sync(0xffffffffu, s, m);
            s2 += __shfl_xor_sync(0xffffffffu, s2, m);
        }
        float mu = s * (1.f / 64.f);
        float var = s2 * (1.f / 64.f) - mu * mu;
        float inv = rsqrtf(var + 1e-5f);
        int row = idx_s[tn * 4 + i];
        if (row >= 0) {
            float* xr = g_x + (b * NN + row) * DD + td * 4;
            float4 xold = *(const float4*)xr;
            float4 o;
            o.x = fmaxf((acc[i][0] - mu) * inv * lng[0] + lnb[0], 0.f) + xold.x;
            o.y = fmaxf((acc[i][1] - mu) * inv * lng[1] + lnb[1], 0.f) + xold.y;
            o.z = fmaxf((acc[i][2] - mu) * inv * lng[2] + lnb[2], 0.f) + xold.z;
            o.w = fmaxf((acc[i][3] - mu) * inv * lng[3] + lnb[3], 0.f) + xold.w;
            *(float4*)xr = o;
            *(float4*)(g_agg + (b * NN + row) * DD + td * 4) =
                make_float4(0.f, 0.f, 0.f, 0.f);
        }
    }
}

// ---------------------------------------------------------------------------
// final: out = relu([x ; query] @ mlp_w + mlp_b); query part precomputed.
// ---------------------------------------------------------------------------
__global__ void final_kernel(const float* __restrict__ mlp_w,
                             float* __restrict__ out) {
    extern __shared__ float smem[];
    float* W_s = smem;             // [64][128] = 32KB
    float* x_s = smem + 64 * 128;  // [k][node] = 16KB
    int b = blockIdx.y;
    int n0 = blockIdx.x * 64;
    int t = threadIdx.x;

    const float4* Wg = (const float4*)mlp_w;
    float4* Ws4 = (float4*)W_s;
#pragma unroll
    for (int i = 0; i < 8; i++) Ws4[t + i * 256] = Wg[t + i * 256];

    const float* xb = g_x + (b * NN + n0) * DD;
    int nl = t & 63;
    int c0 = t >> 6;
#pragma unroll
    for (int i = 0; i < 4; i++) {
        int cc = c0 + i * 4;
        float4 v = *(const float4*)&xb[nl * DD + cc * 4];
        x_s[(cc * 4 + 0) * 64 + nl] = v.x;
        x_s[(cc * 4 + 1) * 64 + nl] = v.y;
        x_s[(cc * 4 + 2) * 64 + nl] = v.z;
        x_s[(cc * 4 + 3) * 64 + nl] = v.w;
    }
    __syncthreads();

    int tn = t >> 4;  // 16 node groups (4 nodes each)
    int td = t & 15;  // 16 dim groups (8 dims each)
    float acc[4][8];
#pragma unroll
    for (int i = 0; i < 4; i++)
#pragma unroll
        for (int j = 0; j < 8; j++) acc[i][j] = 0.f;

#pragma unroll 4
    for (int k = 0; k < 64; ++k) {
        const float4 a4 = *(const float4*)(x_s + k * 64 + tn * 4);
        const float4 w0 = *(const float4*)(W_s + k * 128 + td * 8);
        const float4 w1 = *(const float4*)(W_s + k * 128 + td * 8 + 4);
        float aa[4] = {a4.x, a4.y, a4.z, a4.w};
        float ww[8] = {w0.x, w0.y, w0.z, w0.w, w1.x, w1.y, w1.z, w1.w};
#pragma unroll
        for (int i = 0; i < 4; i++)
#pragma unroll
            for (int j = 0; j < 8; j++)
                acc[i][j] = fmaf(aa[i], ww[j], acc[i][j]);
    }

    float qp[8];
    const float4 q0 = *(const float4*)&g_qpart[b * 128 + td * 8];
    const float4 q1 = *(const float4*)&g_qpart[b * 128 + td * 8 + 4];
    qp[0] = q0.x; qp[1] = q0.y; qp[2] = q0.z; qp[3] = q0.w;
    qp[4] = q1.x; qp[5] = q1.y; qp[6] = q1.z; qp[7] = q1.w;

#pragma unroll
    for (int i = 0; i < 4; i++) {
        int n = n0 + tn * 4 + i;
        float* op = out + ((long)(b * NN + n)) * 128 + td * 8;
        float4 o0, o1;
        o0.x = fmaxf(acc[i][0] + qp[0], 0.f);
        o0.y = fmaxf(acc[i][1] + qp[1], 0.f);
        o0.z = fmaxf(acc[i][2] + qp[2], 0.f);
        o0.w = fmaxf(acc[i][3] + qp[3], 0.f);
        o1.x = fmaxf(acc[i][4] + qp[4], 0.f);
        o1.y = fmaxf(acc[i][5] + qp[5], 0.f);
        o1.z = fmaxf(acc[i][6] + qp[6], 0.f);
        o1.w = fmaxf(acc[i][7] + qp[7], 0.f);
        *(float4*)op = o0;
        *(float4*)(op + 4) = o1;
    }
}

// ---------------------------------------------------------------------------
extern "C" void kernel_launch(void* const* d_in, const int* in_sizes, int n_in,
                              void* d_out, int out_size) {
    const float* rel_reps = (const float*)d_in[0];
    const int* h_index = (const int*)d_in[1];
    const int* r_index = (const int*)d_in[2];
    const int* edge_index = (const int*)d_in[3];
    const int* edge_type = (const int*)d_in[4];
    const float* pw1 = (const float*)d_in[5];
    const float* pb1 = (const float*)d_in[6];
    const float* pw2 = (const float*)d_in[7];
    const float* pb2 = (const float*)d_in[8];
    const float* lin_w = (const float*)d_in[9];
    const float* lin_b = (const float*)d_in[10];
    const float* ln_g = (const float*)d_in[11];
    const float* ln_b = (const float*)d_in[12];
    const float* mlp_w = (const float*)d_in[13];
    const float* mlp_b = (const float*)d_in[14];
    float* out = (float*)d_out;

    cudaFuncSetAttribute(linear_kernel,
                         cudaFuncAttributeMaxDynamicSharedMemorySize, 65536);
    cudaFuncSetAttribute(final_kernel,
                         cudaFuncAttributeMaxDynamicSharedMemorySize, 49152);

    prep_kernel<<<1, 256>>>(rel_reps, r_index, h_index, mlp_w, mlp_b, lin_b,
                            ln_g, ln_b);
    csr_clear<<<SCANB, 256>>>();
    csr_hist<<<(EE + 255) / 256, 256>>>(edge_index);
    csr_scan1<<<SCANB, 256>>>();
    csr_scan2<<<1, 256>>>();
    csr_scan3<<<SCANB, 256>>>();
    csr_scatter<<<(EE + 255) / 256, 256>>>(edge_index);
    init_x<<<(BB * NN * DD / 4 + 255) / 256, 256>>>(h_index);
    for (int l = 0; l < LLAYERS; l++) {
        relproj_kernel<<<BB * RR, 64>>>(rel_reps, pw1, pb1, pw2, pb2, l);
        gather_kernel<<<BB * NN / 8, 256>>>(edge_index, edge_type, h_index);
        compact_kernel<<<(BB * NN + 255) / 256, 256>>>();
        linear_kernel<<<dim3((NN + 63) / 64, BB), 256, 65536>>>(lin_w, lin_b,
                                                                ln_g, ln_b, l);
    }
    final_kernel<<<dim3(NN / 64, BB), 256, 49152>>>(mlp_w, out);
}

// round 9
// speedup vs baseline: 1.5551x; 1.0055x over previous
#include <cuda_runtime.h>

#define BB 2
#define NN 40000
#define EE 400000
#define RR 64
#define DD 64
#define LLAYERS 6
#define MASKW 1250   // (NN+31)/32
#define SCANB 157    // (NN+255)/256

#define FMA2(acc, a, b) \
    asm("fma.rn.f32x2 %0, %1, %2, %0;" : "+l"(acc) : "l"(a), "l"(b))
#define PACK2(dst, lo, hi) \
    asm("mov.b64 %0, {%1,%2};" : "=l"(dst) : "r"(__float_as_uint(lo)), "r"(__float_as_uint(hi)))
#define DUP2(dst, v) \
    asm("mov.b64 %0, {%1,%1};" : "=l"(dst) : "r"(__float_as_uint(v)))
#define UNPACK2(lo, hi, src)                          \
    do {                                              \
        unsigned _ulo, _uhi;                          \
        asm("mov.b64 {%0,%1}, %2;"                    \
            : "=r"(_ulo), "=r"(_uhi) : "l"(src));     \
        lo = __uint_as_float(_ulo);                   \
        hi = __uint_as_float(_uhi);                   \
    } while (0)

// Scratch (allocation-free rule: __device__ globals)
__device__ __align__(16) float g_x[BB * NN * DD];    // 20.5 MB
__device__ __align__(16) float g_agg[BB * NN * DD];  // 20.5 MB (invariant: list rows zero at entry of each gather)
__device__ __align__(16) float g_rel[BB * RR * DD];
__device__ __align__(16) float g_query[BB * DD];
__device__ __align__(16) float g_qpart[BB * 2 * DD];
__device__ unsigned g_mask[BB * MASKW];  // bit set => x row may be nonzero
__device__ int g_list[BB * NN];
__device__ int g_count[BB];
__device__ int g_dense;  // 1 => zero rows would produce nonzero output
// CSR by dst (shared by both batches — same graph)
__device__ int g_cnt[NN];
__device__ int g_fill[NN];
__device__ int g_csr_ptr[NN + 1];
__device__ int g_csr_eid[EE];
__device__ int g_bsum[SCANB + 3];

// ---------------------------------------------------------------------------
// prep
// ---------------------------------------------------------------------------
__global__ void prep_kernel(const float* __restrict__ rel_reps,
                            const int* __restrict__ r_index,
                            const int* __restrict__ h_index,
                            const float* __restrict__ mlp_w,
                            const float* __restrict__ mlp_b,
                            const float* __restrict__ lin_b,
                            const float* __restrict__ ln_g,
                            const float* __restrict__ ln_b) {
    __shared__ float q_s[BB * DD];
    int t = threadIdx.x;  // 256
    for (int i = t; i < BB * MASKW; i += 256) g_mask[i] = 0u;
    if (t < BB * DD) {
        int b = t / DD, d = t % DD;
        float v = rel_reps[(b * RR + r_index[b]) * DD + d];
        g_query[t] = v;
        q_s[t] = v;
    }
    __syncthreads();
    if (t < BB) {
        int h = h_index[t];
        g_mask[t * MASKW + (h >> 5)] = 1u << (h & 31);
    }
    if (t == 0) {
        int dense = 0;
        for (int l = 0; l < LLAYERS; l++) {
            const float* lb = lin_b + l * DD;
            float mu = 0.f;
            for (int d = 0; d < DD; d++) mu += lb[d];
            mu *= (1.f / DD);
            float var = 0.f;
            for (int d = 0; d < DD; d++) {
                float dv = lb[d] - mu;
                var += dv * dv;
            }
            var *= (1.f / DD);
            float inv = rsqrtf(var + 1e-5f);
            for (int d = 0; d < DD; d++) {
                float o = (lb[d] - mu) * inv * ln_g[l * DD + d] + ln_b[l * DD + d];
                if (o > 0.f) dense = 1;
            }
        }
        g_dense = dense;
    }
    int b = t / 128, e = t % 128;
    float acc = mlp_b[e];
#pragma unroll
    for (int k = 0; k < DD; k++)
        acc = fmaf(q_s[b * DD + k], mlp_w[(DD + k) * 128 + e], acc);
    g_qpart[b * 128 + e] = acc;
}

// ---------------------------------------------------------------------------
// CSR build (once per launch; replay-safe). Multi-block 3-stage scan.
// ---------------------------------------------------------------------------
__global__ void csr_clear() {
    int n = blockIdx.x * 256 + threadIdx.x;
    if (n < NN) g_cnt[n] = 0;
}
__global__ void csr_hist(const int* __restrict__ edge_index) {
    int e = blockIdx.x * 256 + threadIdx.x;
    if (e < EE) atomicAdd(&g_cnt[__ldg(&edge_index[EE + e])], 1);
}
__global__ void csr_scan1() {
    __shared__ int sh[256];
    int t = threadIdx.x;
    int i = blockIdx.x * 256 + t;
    int v = (i < NN) ? g_cnt[i] : 0;
    sh[t] = v;
    __syncthreads();
#pragma unroll
    for (int off = 1; off < 256; off <<= 1) {
        int u = (t >= off) ? sh[t - off] : 0;
        __syncthreads();
        sh[t] += u;
        __syncthreads();
    }
    if (t == 255) g_bsum[blockIdx.x] = sh[255];
    if (i < NN) g_csr_ptr[i] = sh[t] - v;
}
__global__ void csr_scan2() {
    __shared__ int sh[256];
    int t = threadIdx.x;
    int v = (t < SCANB) ? g_bsum[t] : 0;
    sh[t] = v;
    __syncthreads();
#pragma unroll
    for (int off = 1; off < 256; off <<= 1) {
        int u = (t >= off) ? sh[t - off] : 0;
        __syncthreads();
        sh[t] += u;
        __syncthreads();
    }
    if (t < SCANB) g_bsum[t] = sh[t] - v;
}
__global__ void csr_scan3() {
    int i = blockIdx.x * 256 + threadIdx.x;
    if (i < NN) {
        int p = g_csr_ptr[i] + g_bsum[blockIdx.x];
        g_csr_ptr[i] = p;
        g_fill[i] = p;
    }
    if (i == 0) g_csr_ptr[NN] = EE;
}
__global__ void csr_scatter(const int* __restrict__ edge_index) {
    int e = blockIdx.x * 256 + threadIdx.x;
    if (e >= EE) return;
    int pos = atomicAdd(&g_fill[__ldg(&edge_index[EE + e])], 1);
    g_csr_eid[pos] = e;
}

// ---------------------------------------------------------------------------
// init x: zeros everywhere, query at h_index[b]
// ---------------------------------------------------------------------------
__global__ void init_x(const int* __restrict__ h_index) {
    int gid = blockIdx.x * 256 + threadIdx.x;
    const int per_b = NN * DD / 4;
    if (gid >= BB * per_b) return;
    int b = gid / per_b;
    int r = gid - b * per_b;
    int n = r >> 4;
    int d4 = r & 15;
    float4 v = make_float4(0.f, 0.f, 0.f, 0.f);
    if (n == __ldg(&h_index[b]))
        v = *(const float4*)&g_query[b * DD + d4 * 4];
    ((float4*)g_x)[gid] = v;
}

// ---------------------------------------------------------------------------
// per-layer relation projection + count reset
// ---------------------------------------------------------------------------
__global__ void relproj_kernel(const float* __restrict__ rel_reps,
                               const float* __restrict__ pw1,
                               const float* __restrict__ pb1,
                               const float* __restrict__ pw2,
                               const float* __restrict__ pb2, int l) {
    int br = blockIdx.x;
    int b = br >> 6;
    int e = threadIdx.x;  // 64
    __shared__ float in_s[DD];
    __shared__ float hid_s[DD];
    in_s[e] = rel_reps[br * DD + e];
    __syncthreads();
    const float* W1 = pw1 + l * DD * DD;
    float acc = pb1[l * DD + e];
#pragma unroll 16
    for (int k = 0; k < DD; k++) acc = fmaf(in_s[k], W1[k * DD + e], acc);
    hid_s[e] = fmaxf(acc, 0.f);
    __syncthreads();
    const float* W2 = pw2 + l * DD * DD;
    float acc2 = pb2[l * DD + e];
#pragma unroll 16
    for (int k = 0; k < DD; k++) acc2 = fmaf(hid_s[k], W2[k * DD + e], acc2);
    g_rel[br * DD + e] = acc2;

    if ((br & 63) == 0 && e == 0) g_count[b] = 0;
}

// ---------------------------------------------------------------------------
// gather message: warp per (b,dst). Lanes probe 32 edges' src masks in
// parallel; active edges accumulate x[src]*rel[type] via packed f32x2 FMA.
// ---------------------------------------------------------------------------
__global__ void __launch_bounds__(256)
gather_kernel(const int* __restrict__ edge_index,
              const int* __restrict__ edge_type,
              const int* __restrict__ h_index) {
    const unsigned FULL = 0xffffffffu;
    int w = blockIdx.x * 8 + (threadIdx.x >> 5);  // grid covers BB*NN exactly
    int lane = threadIdx.x & 31;
    int b = (w >= NN) ? 1 : 0;
    int dst = w - b * NN;
    const unsigned* mask = g_mask + b * MASKW;
    int beg = __ldg(&g_csr_ptr[dst]);
    int end = __ldg(&g_csr_ptr[dst + 1]);
    int h = __ldg(&h_index[b]);
    unsigned long long acc = 0ull;  // packed f32x2 {d0,d1}
    bool any = false;
    for (int base = beg; base < end; base += 32) {
        int i = base + lane;
        int eid = 0, src = 0, ty = 0;
        bool a = false;
        if (i < end) {
            eid = __ldg(&g_csr_eid[i]);
            src = __ldg(&edge_index[eid]);
            a = (mask[src >> 5] >> (src & 31)) & 1u;
        }
        unsigned ball = __ballot_sync(FULL, a);
        if (a) ty = __ldg(&edge_type[eid]);
        any |= (ball != 0);
        while (ball) {
            int l = __ffs(ball) - 1;
            ball &= ball - 1;
            int s = __shfl_sync(FULL, src, l);
            int tt = __shfl_sync(FULL, ty, l);
            unsigned long long xv =
                *(const unsigned long long*)&g_x[(b * NN + s) * DD + lane * 2];
            unsigned long long rv = *(const unsigned long long*)&g_rel
                [(b * RR + tt) * DD + lane * 2];
            FMA2(acc, xv, rv);
        }
    }
    float a0, a1;
    UNPACK2(a0, a1, acc);
    if (dst == h) {
        float2 q = *(const float2*)&g_query[b * DD + lane * 2];
        a0 += q.x;
        a1 += q.y;
        any = true;
    }
    if (any) {
        *(float2*)&g_agg[(b * NN + dst) * DD + lane * 2] =
            make_float2(a0, a1);
        if (lane == 0) {
            unsigned bit = 1u << (dst & 31);
            if (!(mask[dst >> 5] & bit))
                atomicOr(&g_mask[b * MASKW + (dst >> 5)], bit);
        }
    }
}

// ---------------------------------------------------------------------------
// compact: mask -> list, warp-aggregated, order-preserving within warp.
// ---------------------------------------------------------------------------
__global__ void compact_kernel() {
    int gid = blockIdx.x * 256 + threadIdx.x;
    if (gid >= BB * NN) return;
    int b = gid / NN;
    int n = gid - b * NN;
    bool act;
    if (g_dense) {
        act = true;
        if ((n & 31) == 0) g_mask[b * MASKW + (n >> 5)] = 0xffffffffu;
    } else {
        act = (g_mask[b * MASKW + (n >> 5)] >> (n & 31)) & 1u;
    }
    unsigned bal = __ballot_sync(0xffffffffu, act);
    if (!bal) return;
    int lane = threadIdx.x & 31;
    int pos = 0;
    if (lane == 0) pos = atomicAdd(&g_count[b], __popc(bal));
    pos = __shfl_sync(0xffffffffu, pos, 0);
    if (act)
        g_list[b * NN + pos + __popc(bal & ((1u << lane) - 1u))] = n;
}

// ---------------------------------------------------------------------------
// fused linear (R3 shape + f32x2): 64 list rows, 256 threads, 4x4 tile.
// Inner loop: 8 packed f32x2 FMA instead of 16 FFMA.
// ---------------------------------------------------------------------------
__global__ void linear_kernel(const float* __restrict__ lin_w,
                              const float* __restrict__ lin_b,
                              const float* __restrict__ ln_g,
                              const float* __restrict__ ln_b, int l) {
    extern __shared__ float smem[];
    float* W_s = smem;               // [128][64] = 32KB
    float* cat_s = smem + 128 * 64;  // [k][node] transposed = 32KB
    __shared__ int idx_s[64];
    int b = blockIdx.y;
    int base = blockIdx.x * 64;
    int t = threadIdx.x;  // 256
    int cnt = g_count[b];
    if (base >= cnt) return;

    if (t < 64) idx_s[t] = (base + t < cnt) ? g_list[b * NN + base + t] : -1;

    const float4* Wg = (const float4*)(lin_w + l * 128 * 64);
    float4* Ws4 = (float4*)W_s;
#pragma unroll
    for (int i = 0; i < 8; i++) Ws4[t + i * 256] = Wg[t + i * 256];
    __syncthreads();

    int nl = t & 63;
    int c0 = t >> 6;  // 0..3
    int idx = idx_s[nl];
    const float* xb = g_x + (b * NN + idx) * DD;
    const float* ab = g_agg + (b * NN + idx) * DD;
#pragma unroll
    for (int i = 0; i < 4; i++) {
        int cc = c0 + i * 4;  // float4 col 0..15
        float4 v = make_float4(0.f, 0.f, 0.f, 0.f);
        float4 a = make_float4(0.f, 0.f, 0.f, 0.f);
        if (idx >= 0) {
            v = *(const float4*)&xb[cc * 4];
            a = *(const float4*)&ab[cc * 4];
        }
        cat_s[(cc * 4 + 0) * 64 + nl] = v.x;
        cat_s[(cc * 4 + 1) * 64 + nl] = v.y;
        cat_s[(cc * 4 + 2) * 64 + nl] = v.z;
        cat_s[(cc * 4 + 3) * 64 + nl] = v.w;
        cat_s[(64 + cc * 4 + 0) * 64 + nl] = a.x;
        cat_s[(64 + cc * 4 + 1) * 64 + nl] = a.y;
        cat_s[(64 + cc * 4 + 2) * 64 + nl] = a.z;
        cat_s[(64 + cc * 4 + 3) * 64 + nl] = a.w;
    }
    __syncthreads();

    int tn = t >> 4;  // node group (4 nodes)
    int td = t & 15;  // dim group  (4 dims)
    float4 bias4 = *(const float4*)&lin_b[l * 64 + td * 4];
    unsigned long long accp[4][2];
    {
        unsigned long long b01, b23;
        PACK2(b01, bias4.x, bias4.y);
        PACK2(b23, bias4.z, bias4.w);
#pragma unroll
        for (int i = 0; i < 4; i++) {
            accp[i][0] = b01;
            accp[i][1] = b23;
        }
    }

#pragma unroll 4
    for (int k = 0; k < 128; ++k) {
        const float4 a4 = *(const float4*)(cat_s + k * 64 + tn * 4);
        const ulonglong2 w2 = *(const ulonglong2*)(W_s + k * 64 + td * 4);
        float aa[4] = {a4.x, a4.y, a4.z, a4.w};
#pragma unroll
        for (int i = 0; i < 4; i++) {
            unsigned long long av;
            DUP2(av, aa[i]);
            FMA2(accp[i][0], av, w2.x);
            FMA2(accp[i][1], av, w2.y);
        }
    }

    float acc[4][4];
#pragma unroll
    for (int i = 0; i < 4; i++) {
        UNPACK2(acc[i][0], acc[i][1], accp[i][0]);
        UNPACK2(acc[i][2], acc[i][3], accp[i][1]);
    }

    float4 g4 = *(const float4*)&ln_g[l * 64 + td * 4];
    float4 bb4 = *(const float4*)&ln_b[l * 64 + td * 4];
    float lng[4] = {g4.x, g4.y, g4.z, g4.w};
    float lnb[4] = {bb4.x, bb4.y, bb4.z, bb4.w};
#pragma unroll
    for (int i = 0; i < 4; i++) {
        float s = acc[i][0] + acc[i][1] + acc[i][2] + acc[i][3];
        float s2 = acc[i][0] * acc[i][0] + acc[i][1] * acc[i][1] +
                   acc[i][2] * acc[i][2] + acc[i][3] * acc[i][3];
#pragma unroll
        for (int m = 1; m < 16; m <<= 1) {
            s += __shfl_xor_sync(0xffffffffu, s, m);
            s2 += __shfl_xor_sync(0xffffffffu, s2, m);
        }
        float mu = s * (1.f / 64.f);
        float var = s2 * (1.f / 64.f) - mu * mu;
        float inv = rsqrtf(var + 1e-5f);
        int row = idx_s[tn * 4 + i];
        if (row >= 0) {
            float* xr = g_x + (b * NN + row) * DD + td * 4;
            float4 xold = *(const float4*)xr;
            float4 o;
            o.x = fmaxf((acc[i][0] - mu) * inv * lng[0] + lnb[0], 0.f) + xold.x;
            o.y = fmaxf((acc[i][1] - mu) * inv * lng[1] + lnb[1], 0.f) + xold.y;
            o.z = fmaxf((acc[i][2] - mu) * inv * lng[2] + lnb[2], 0.f) + xold.z;
            o.w = fmaxf((acc[i][3] - mu) * inv * lng[3] + lnb[3], 0.f) + xold.w;
            *(float4*)xr = o;
            *(float4*)(g_agg + (b * NN + row) * DD + td * 4) =
                make_float4(0.f, 0.f, 0.f, 0.f);
        }
    }
}

// ---------------------------------------------------------------------------
// final: out = relu([x ; query] @ mlp_w + mlp_b); query part precomputed.
// f32x2 inner loop.
// ---------------------------------------------------------------------------
__global__ void final_kernel(const float* __restrict__ mlp_w,
                             float* __restrict__ out) {
    extern __shared__ float smem[];
    float* W_s = smem;             // [64][128] = 32KB
    float* x_s = smem + 64 * 128;  // [k][node] = 16KB
    int b = blockIdx.y;
    int n0 = blockIdx.x * 64;
    int t = threadIdx.x;

    const float4* Wg = (const float4*)mlp_w;
    float4* Ws4 = (float4*)W_s;
#pragma unroll
    for (int i = 0; i < 8; i++) Ws4[t + i * 256] = Wg[t + i * 256];

    const float* xb = g_x + (b * NN + n0) * DD;
    int nl = t & 63;
    int c0 = t >> 6;
#pragma unroll
    for (int i = 0; i < 4; i++) {
        int cc = c0 + i * 4;
        float4 v = *(const float4*)&xb[nl * DD + cc * 4];
        x_s[(cc * 4 + 0) * 64 + nl] = v.x;
        x_s[(cc * 4 + 1) * 64 + nl] = v.y;
        x_s[(cc * 4 + 2) * 64 + nl] = v.z;
        x_s[(cc * 4 + 3) * 64 + nl] = v.w;
    }
    __syncthreads();

    int tn = t >> 4;  // 16 node groups (4 nodes each)
    int td = t & 15;  // 16 dim groups (8 dims each)
    unsigned long long accp[4][4];
#pragma unroll
    for (int i = 0; i < 4; i++)
#pragma unroll
        for (int j = 0; j < 4; j++) accp[i][j] = 0ull;

#pragma unroll 4
    for (int k = 0; k < 64; ++k) {
        const float4 a4 = *(const float4*)(x_s + k * 64 + tn * 4);
        const ulonglong2 w01 = *(const ulonglong2*)(W_s + k * 128 + td * 8);
        const ulonglong2 w23 =
            *(const ulonglong2*)(W_s + k * 128 + td * 8 + 4);
        float aa[4] = {a4.x, a4.y, a4.z, a4.w};
#pragma unroll
        for (int i = 0; i < 4; i++) {
            unsigned long long av;
            DUP2(av, aa[i]);
            FMA2(accp[i][0], av, w01.x);
            FMA2(accp[i][1], av, w01.y);
            FMA2(accp[i][2], av, w23.x);
            FMA2(accp[i][3], av, w23.y);
        }
    }

    float qp[8];
    const float4 q0 = *(const float4*)&g_qpart[b * 128 + td * 8];
    const float4 q1 = *(const float4*)&g_qpart[b * 128 + td * 8 + 4];
    qp[0] = q0.x; qp[1] = q0.y; qp[2] = q0.z; qp[3] = q0.w;
    qp[4] = q1.x; qp[5] = q1.y; qp[6] = q1.z; qp[7] = q1.w;

#pragma unroll
    for (int i = 0; i < 4; i++) {
        float acc[8];
        UNPACK2(acc[0], acc[1], accp[i][0]);
        UNPACK2(acc[2], acc[3], accp[i][1]);
        UNPACK2(acc[4], acc[5], accp[i][2]);
        UNPACK2(acc[6], acc[7], accp[i][3]);
        int n = n0 + tn * 4 + i;
        float* op = out + ((long)(b * NN + n)) * 128 + td * 8;
        float4 o0, o1;
        o0.x = fmaxf(acc[0] + qp[0], 0.f);
        o0.y = fmaxf(acc[1] + qp[1], 0.f);
        o0.z = fmaxf(acc[2] + qp[2], 0.f);
        o0.w = fmaxf(acc[3] + qp[3], 0.f);
        o1.x = fmaxf(acc[4] + qp[4], 0.f);
        o1.y = fmaxf(acc[5] + qp[5], 0.f);
        o1.z = fmaxf(acc[6] + qp[6], 0.f);
        o1.w = fmaxf(acc[7] + qp[7], 0.f);
        *(float4*)op = o0;
        *(float4*)(op + 4) = o1;
    }
}

// ---------------------------------------------------------------------------
extern "C" void kernel_launch(void* const* d_in, const int* in_sizes, int n_in,
                              void* d_out, int out_size) {
    const float* rel_reps = (const float*)d_in[0];
    const int* h_index = (const int*)d_in[1];
    const int* r_index = (const int*)d_in[2];
    const int* edge_index = (const int*)d_in[3];
    const int* edge_type = (const int*)d_in[4];
    const float* pw1 = (const float*)d_in[5];
    const float* pb1 = (const float*)d_in[6];
    const float* pw2 = (const float*)d_in[7];
    const float* pb2 = (const float*)d_in[8];
    const float* lin_w = (const float*)d_in[9];
    const float* lin_b = (const float*)d_in[10];
    const float* ln_g = (const float*)d_in[11];
    const float* ln_b = (const float*)d_in[12];
    const float* mlp_w = (const float*)d_in[13];
    const float* mlp_b = (const float*)d_in[14];
    float* out = (float*)d_out;

    cudaFuncSetAttribute(linear_kernel,
                         cudaFuncAttributeMaxDynamicSharedMemorySize, 65536);
    cudaFuncSetAttribute(final_kernel,
                         cudaFuncAttributeMaxDynamicSharedMemorySize, 49152);

    prep_kernel<<<1, 256>>>(rel_reps, r_index, h_index, mlp_w, mlp_b, lin_b,
                            ln_g, ln_b);
    csr_clear<<<SCANB, 256>>>();
    csr_hist<<<(EE + 255) / 256, 256>>>(edge_index);
    csr_scan1<<<SCANB, 256>>>();
    csr_scan2<<<1, 256>>>();
    csr_scan3<<<SCANB, 256>>>();
    csr_scatter<<<(EE + 255) / 256, 256>>>(edge_index);
    init_x<<<(BB * NN * DD / 4 + 255) / 256, 256>>>(h_index);
    for (int l = 0; l < LLAYERS; l++) {
        relproj_kernel<<<BB * RR, 64>>>(rel_reps, pw1, pb1, pw2, pb2, l);
        gather_kernel<<<BB * NN / 8, 256>>>(edge_index, edge_type, h_index);
        compact_kernel<<<(BB * NN + 255) / 256, 256>>>();
        linear_kernel<<<dim3((NN + 63) / 64, BB), 256, 65536>>>(lin_w, lin_b,
                                                                ln_g, ln_b, l);
    }
    final_kernel<<<dim3(NN / 64, BB), 256, 49152>>>(mlp_w, out);
}

// round 10
// speedup vs baseline: 1.5908x; 1.0229x over previous
#include <cuda_runtime.h>

#define BB 2
#define NN 40000
#define EE 400000
#define RR 64
#define DD 64
#define LLAYERS 6
#define MASKW 1250   // (NN+31)/32
#define SCANB 157    // (NN+255)/256

#define FMA2(acc, a, b) \
    asm("fma.rn.f32x2 %0, %1, %2, %0;" : "+l"(acc) : "l"(a), "l"(b))
#define PACK2(dst, lo, hi) \
    asm("mov.b64 %0, {%1,%2};" : "=l"(dst) : "r"(__float_as_uint(lo)), "r"(__float_as_uint(hi)))
#define DUP2(dst, v) \
    asm("mov.b64 %0, {%1,%1};" : "=l"(dst) : "r"(__float_as_uint(v)))
#define UNPACK2(lo, hi, src)                          \
    do {                                              \
        unsigned _ulo, _uhi;                          \
        asm("mov.b64 {%0,%1}, %2;"                    \
            : "=r"(_ulo), "=r"(_uhi) : "l"(src));     \
        lo = __uint_as_float(_ulo);                   \
        hi = __uint_as_float(_uhi);                   \
    } while (0)

// Scratch (allocation-free rule: __device__ globals)
__device__ __align__(16) float g_x[BB * NN * DD];    // 20.5 MB
__device__ __align__(16) float g_agg[BB * NN * DD];  // 20.5 MB (listed rows zeroed after each linear)
__device__ __align__(16) float g_rel[LLAYERS * BB * RR * DD];  // all layers upfront
__device__ __align__(16) float g_query[BB * DD];
__device__ __align__(16) float g_qpart[BB * 2 * DD];
__device__ unsigned g_mask[BB * MASKW];  // bit set <=> node is in g_list
__device__ int g_list[BB * NN];          // persistent, monotone across layers
__device__ int g_count[BB];
__device__ int g_dense;  // 1 => zero rows would produce nonzero output
// CSR by dst (shared by both batches — same graph)
__device__ int g_cnt[NN];  // zero at every launch entry/exit (BSS + scan1 restore)
__device__ int g_fill[NN];
__device__ int g_csr_ptr[NN + 1];
__device__ int g_csr_eid[EE];
__device__ int g_bsum[SCANB + 3];

// ---------------------------------------------------------------------------
// prep: masks, query, dense flag, list seed {h}, qpart
// ---------------------------------------------------------------------------
__global__ void prep_kernel(const float* __restrict__ rel_reps,
                            const int* __restrict__ r_index,
                            const int* __restrict__ h_index,
                            const float* __restrict__ mlp_w,
                            const float* __restrict__ mlp_b,
                            const float* __restrict__ lin_b,
                            const float* __restrict__ ln_g,
                            const float* __restrict__ ln_b) {
    __shared__ float q_s[BB * DD];
    int t = threadIdx.x;  // 256
    for (int i = t; i < BB * MASKW; i += 256) g_mask[i] = 0u;
    if (t < BB * DD) {
        int b = t / DD, d = t % DD;
        float v = rel_reps[(b * RR + r_index[b]) * DD + d];
        g_query[t] = v;
        q_s[t] = v;
    }
    if (t == 0) {
        int dense = 0;
        for (int l = 0; l < LLAYERS; l++) {
            const float* lb = lin_b + l * DD;
            float mu = 0.f;
            for (int d = 0; d < DD; d++) mu += lb[d];
            mu *= (1.f / DD);
            float var = 0.f;
            for (int d = 0; d < DD; d++) {
                float dv = lb[d] - mu;
                var += dv * dv;
            }
            var *= (1.f / DD);
            float inv = rsqrtf(var + 1e-5f);
            for (int d = 0; d < DD; d++) {
                float o = (lb[d] - mu) * inv * ln_g[l * DD + d] + ln_b[l * DD + d];
                if (o > 0.f) dense = 1;
            }
        }
        g_dense = dense;
    }
    __syncthreads();
    if (t < BB) {
        int h = h_index[t];
        g_mask[t * MASKW + (h >> 5)] = 1u << (h & 31);
        g_count[t] = g_dense ? NN : 1;
        g_list[t * NN] = h;
    }
    int b = t / 128, e = t % 128;
    float acc = mlp_b[e];
#pragma unroll
    for (int k = 0; k < DD; k++)
        acc = fmaf(q_s[b * DD + k], mlp_w[(DD + k) * 128 + e], acc);
    g_qpart[b * 128 + e] = acc;
}

// ---------------------------------------------------------------------------
// CSR build. g_cnt is zero at entry (BSS first time; scan1 re-zeroes after).
// ---------------------------------------------------------------------------
__global__ void csr_hist(const int* __restrict__ edge_index) {
    int e = blockIdx.x * 256 + threadIdx.x;
    if (e < EE) atomicAdd(&g_cnt[__ldg(&edge_index[EE + e])], 1);
}
__global__ void csr_scan1() {
    __shared__ int sh[256];
    int t = threadIdx.x;
    int i = blockIdx.x * 256 + t;
    int v = 0;
    if (i < NN) {
        v = g_cnt[i];
        g_cnt[i] = 0;  // restore zero for next launch/replay
    }
    sh[t] = v;
    __syncthreads();
#pragma unroll
    for (int off = 1; off < 256; off <<= 1) {
        int u = (t >= off) ? sh[t - off] : 0;
        __syncthreads();
        sh[t] += u;
        __syncthreads();
    }
    if (t == 255) g_bsum[blockIdx.x] = sh[255];
    if (i < NN) g_csr_ptr[i] = sh[t] - v;
}
__global__ void csr_scan2() {
    __shared__ int sh[256];
    int t = threadIdx.x;
    int v = (t < SCANB) ? g_bsum[t] : 0;
    sh[t] = v;
    __syncthreads();
#pragma unroll
    for (int off = 1; off < 256; off <<= 1) {
        int u = (t >= off) ? sh[t - off] : 0;
        __syncthreads();
        sh[t] += u;
        __syncthreads();
    }
    if (t < SCANB) g_bsum[t] = sh[t] - v;
}
__global__ void csr_scan3() {
    int i = blockIdx.x * 256 + threadIdx.x;
    if (i < NN) {
        int p = g_csr_ptr[i] + g_bsum[blockIdx.x];
        g_csr_ptr[i] = p;
        g_fill[i] = p;
    }
    if (i == 0) g_csr_ptr[NN] = EE;
}
__global__ void csr_scatter(const int* __restrict__ edge_index) {
    int e = blockIdx.x * 256 + threadIdx.x;
    if (e >= EE) return;
    int pos = atomicAdd(&g_fill[__ldg(&edge_index[EE + e])], 1);
    g_csr_eid[pos] = e;
}

// ---------------------------------------------------------------------------
// init x: zeros everywhere, query at h_index[b].
// Dense fallback: identity list + all-ones mask.
// ---------------------------------------------------------------------------
__global__ void init_x(const int* __restrict__ h_index) {
    int gid = blockIdx.x * 256 + threadIdx.x;
    const int per_b = NN * DD / 4;
    if (gid >= BB * per_b) return;
    if (g_dense) {
        if (gid < BB * NN) g_list[gid] = gid % NN;
        if (gid < BB * MASKW) g_mask[gid] = 0xffffffffu;
    }
    int b = gid / per_b;
    int r = gid - b * per_b;
    int n = r >> 4;
    int d4 = r & 15;
    float4 v = make_float4(0.f, 0.f, 0.f, 0.f);
    if (n == __ldg(&h_index[b]))
        v = *(const float4*)&g_query[b * DD + d4 * 4];
    ((float4*)g_x)[gid] = v;
}

// ---------------------------------------------------------------------------
// ALL layers' relation projections in one kernel (depend only on inputs).
// block = (l, b, r); 64 threads.
// ---------------------------------------------------------------------------
__global__ void relproj_all(const float* __restrict__ rel_reps,
                            const float* __restrict__ pw1,
                            const float* __restrict__ pb1,
                            const float* __restrict__ pw2,
                            const float* __restrict__ pb2) {
    int blk = blockIdx.x;           // l*(BB*RR) + br
    int l = blk / (BB * RR);
    int br = blk - l * (BB * RR);
    int e = threadIdx.x;  // 64
    __shared__ float in_s[DD];
    __shared__ float hid_s[DD];
    in_s[e] = rel_reps[br * DD + e];
    __syncthreads();
    const float* W1 = pw1 + l * DD * DD;
    float acc = pb1[l * DD + e];
#pragma unroll 16
    for (int k = 0; k < DD; k++) acc = fmaf(in_s[k], W1[k * DD + e], acc);
    hid_s[e] = fmaxf(acc, 0.f);
    __syncthreads();
    const float* W2 = pw2 + l * DD * DD;
    float acc2 = pb2[l * DD + e];
#pragma unroll 16
    for (int k = 0; k < DD; k++) acc2 = fmaf(hid_s[k], W2[k * DD + e], acc2);
    g_rel[blk * DD + e] = acc2;
}

// ---------------------------------------------------------------------------
// gather message: warp per (b,dst) — each dst owned by exactly ONE warp, so
// list append is race-free. Lanes probe 32 edges' src masks in parallel;
// active edges accumulate x[src]*rel[l,type] via packed f32x2 FMA.
// Newly-touched dsts appended to the persistent list, block-aggregated.
// ---------------------------------------------------------------------------
__global__ void __launch_bounds__(256)
gather_kernel(const int* __restrict__ edge_index,
              const int* __restrict__ edge_type,
              const int* __restrict__ h_index, int l) {
    const unsigned FULL = 0xffffffffu;
    __shared__ int s_list[8];
    __shared__ int s_n;
    if (threadIdx.x == 0) s_n = 0;
    int w = blockIdx.x * 8 + (threadIdx.x >> 5);  // NN%8==0: block = one batch
    int lane = threadIdx.x & 31;
    int b = (w >= NN) ? 1 : 0;
    int dst = w - b * NN;
    const unsigned* mask = g_mask + b * MASKW;
    const float* relb = g_rel + (l * BB + b) * RR * DD;
    int beg = __ldg(&g_csr_ptr[dst]);
    int end = __ldg(&g_csr_ptr[dst + 1]);
    int h = __ldg(&h_index[b]);
    unsigned long long acc = 0ull;  // packed f32x2
    bool any = false;
    __syncthreads();
    for (int base = beg; base < end; base += 32) {
        int i = base + lane;
        int eid = 0, src = 0, ty = 0;
        bool a = false;
        if (i < end) {
            eid = __ldg(&g_csr_eid[i]);
            src = __ldg(&edge_index[eid]);
            a = (mask[src >> 5] >> (src & 31)) & 1u;
        }
        unsigned ball = __ballot_sync(FULL, a);
        if (a) ty = __ldg(&edge_type[eid]);
        any |= (ball != 0);
        while (ball) {
            int lx = __ffs(ball) - 1;
            ball &= ball - 1;
            int s = __shfl_sync(FULL, src, lx);
            int tt = __shfl_sync(FULL, ty, lx);
            unsigned long long xv =
                *(const unsigned long long*)&g_x[(b * NN + s) * DD + lane * 2];
            unsigned long long rv =
                *(const unsigned long long*)&relb[tt * DD + lane * 2];
            FMA2(acc, xv, rv);
        }
    }
    float a0, a1;
    UNPACK2(a0, a1, acc);
    if (dst == h) {
        float2 q = *(const float2*)&g_query[b * DD + lane * 2];
        a0 += q.x;
        a1 += q.y;
        any = true;
    }
    if (any) {
        *(float2*)&g_agg[(b * NN + dst) * DD + lane * 2] = make_float2(a0, a1);
        if (lane == 0) {
            unsigned bit = 1u << (dst & 31);
            if (!(mask[dst >> 5] & bit)) {
                unsigned old = atomicOr(&g_mask[b * MASKW + (dst >> 5)], bit);
                if (!(old & bit)) {
                    int p = atomicAdd(&s_n, 1);
                    s_list[p] = dst;
                }
            }
        }
    }
    __syncthreads();
    // block-aggregated append (all warps same b)
    if (threadIdx.x == 0 && s_n > 0)
        s_list[7] >= 0 ? void(0) : void(0);  // no-op keep
    __shared__ int s_base;
    if (threadIdx.x == 0 && s_n > 0) s_base = atomicAdd(&g_count[b], s_n);
    __syncthreads();
    if ((int)threadIdx.x < s_n) g_list[b * NN + s_base + threadIdx.x] = s_list[threadIdx.x];
}

// ---------------------------------------------------------------------------
// fused linear (R3 shape + f32x2): 64 list rows, 256 threads, 4x4 tile.
// ---------------------------------------------------------------------------
__global__ void linear_kernel(const float* __restrict__ lin_w,
                              const float* __restrict__ lin_b,
                              const float* __restrict__ ln_g,
                              const float* __restrict__ ln_b, int l) {
    extern __shared__ float smem[];
    float* W_s = smem;               // [128][64] = 32KB
    float* cat_s = smem + 128 * 64;  // [k][node] transposed = 32KB
    __shared__ int idx_s[64];
    int b = blockIdx.y;
    int base = blockIdx.x * 64;
    int t = threadIdx.x;  // 256
    int cnt = g_count[b];
    if (base >= cnt) return;

    if (t < 64) idx_s[t] = (base + t < cnt) ? g_list[b * NN + base + t] : -1;

    const float4* Wg = (const float4*)(lin_w + l * 128 * 64);
    float4* Ws4 = (float4*)W_s;
#pragma unroll
    for (int i = 0; i < 8; i++) Ws4[t + i * 256] = Wg[t + i * 256];
    __syncthreads();

    int nl = t & 63;
    int c0 = t >> 6;  // 0..3
    int idx = idx_s[nl];
    const float* xb = g_x + (b * NN + idx) * DD;
    const float* ab = g_agg + (b * NN + idx) * DD;
#pragma unroll
    for (int i = 0; i < 4; i++) {
        int cc = c0 + i * 4;  // float4 col 0..15
        float4 v = make_float4(0.f, 0.f, 0.f, 0.f);
        float4 a = make_float4(0.f, 0.f, 0.f, 0.f);
        if (idx >= 0) {
            v = *(const float4*)&xb[cc * 4];
            a = *(const float4*)&ab[cc * 4];
        }
        cat_s[(cc * 4 + 0) * 64 + nl] = v.x;
        cat_s[(cc * 4 + 1) * 64 + nl] = v.y;
        cat_s[(cc * 4 + 2) * 64 + nl] = v.z;
        cat_s[(cc * 4 + 3) * 64 + nl] = v.w;
        cat_s[(64 + cc * 4 + 0) * 64 + nl] = a.x;
        cat_s[(64 + cc * 4 + 1) * 64 + nl] = a.y;
        cat_s[(64 + cc * 4 + 2) * 64 + nl] = a.z;
        cat_s[(64 + cc * 4 + 3) * 64 + nl] = a.w;
    }
    __syncthreads();

    int tn = t >> 4;  // node group (4 nodes)
    int td = t & 15;  // dim group  (4 dims)
    float4 bias4 = *(const float4*)&lin_b[l * 64 + td * 4];
    unsigned long long accp[4][2];
    {
        unsigned long long b01, b23;
        PACK2(b01, bias4.x, bias4.y);
        PACK2(b23, bias4.z, bias4.w);
#pragma unroll
        for (int i = 0; i < 4; i++) {
            accp[i][0] = b01;
            accp[i][1] = b23;
        }
    }

#pragma unroll 4
    for (int k = 0; k < 128; ++k) {
        const float4 a4 = *(const float4*)(cat_s + k * 64 + tn * 4);
        const ulonglong2 w2 = *(const ulonglong2*)(W_s + k * 64 + td * 4);
        float aa[4] = {a4.x, a4.y, a4.z, a4.w};
#pragma unroll
        for (int i = 0; i < 4; i++) {
            unsigned long long av;
            DUP2(av, aa[i]);
            FMA2(accp[i][0], av, w2.x);
            FMA2(accp[i][1], av, w2.y);
        }
    }

    float acc[4][4];
#pragma unroll
    for (int i = 0; i < 4; i++) {
        UNPACK2(acc[i][0], acc[i][1], accp[i][0]);
        UNPACK2(acc[i][2], acc[i][3], accp[i][1]);
    }

    float4 g4 = *(const float4*)&ln_g[l * 64 + td * 4];
    float4 bb4 = *(const float4*)&ln_b[l * 64 + td * 4];
    float lng[4] = {g4.x, g4.y, g4.z, g4.w};
    float lnb[4] = {bb4.x, bb4.y, bb4.z, bb4.w};
#pragma unroll
    for (int i = 0; i < 4; i++) {
        float s = acc[i][0] + acc[i][1] + acc[i][2] + acc[i][3];
        float s2 = acc[i][0] * acc[i][0] + acc[i][1] * acc[i][1] +
                   acc[i][2] * acc[i][2] + acc[i][3] * acc[i][3];
#pragma unroll
        for (int m = 1; m < 16; m <<= 1) {
            s += __shfl_xor_sync(0xffffffffu, s, m);
            s2 += __shfl_xor_sync(0xffffffffu, s2, m);
        }
        float mu = s * (1.f / 64.f);
        float var = s2 * (1.f / 64.f) - mu * mu;
        float inv = rsqrtf(var + 1e-5f);
        int row = idx_s[tn * 4 + i];
        if (row >= 0) {
            float* xr = g_x + (b * NN + row) * DD + td * 4;
            float4 xold = *(const float4*)xr;
            float4 o;
            o.x = fmaxf((acc[i][0] - mu) * inv * lng[0] + lnb[0], 0.f) + xold.x;
            o.y = fmaxf((acc[i][1] - mu) * inv * lng[1] + lnb[1], 0.f) + xold.y;
            o.z = fmaxf((acc[i][2] - mu) * inv * lng[2] + lnb[2], 0.f) + xold.z;
            o.w = fmaxf((acc[i][3] - mu) * inv * lng[3] + lnb[3], 0.f) + xold.w;
            *(float4*)xr = o;
            *(float4*)(g_agg + (b * NN + row) * DD + td * 4) =
                make_float4(0.f, 0.f, 0.f, 0.f);
        }
    }
}

// ---------------------------------------------------------------------------
// final: out = relu([x ; query] @ mlp_w + mlp_b); query part precomputed.
// ---------------------------------------------------------------------------
__global__ void final_kernel(const float* __restrict__ mlp_w,
                             float* __restrict__ out) {
    extern __shared__ float smem[];
    float* W_s = smem;             // [64][128] = 32KB
    float* x_s = smem + 64 * 128;  // [k][node] = 16KB
    int b = blockIdx.y;
    int n0 = blockIdx.x * 64;
    int t = threadIdx.x;

    const float4* Wg = (const float4*)mlp_w;
    float4* Ws4 = (float4*)W_s;
#pragma unroll
    for (int i = 0; i < 8; i++) Ws4[t + i * 256] = Wg[t + i * 256];

    const float* xb = g_x + (b * NN + n0) * DD;
    int nl = t & 63;
    int c0 = t >> 6;
#pragma unroll
    for (int i = 0; i < 4; i++) {
        int cc = c0 + i * 4;
        float4 v = *(const float4*)&xb[nl * DD + cc * 4];
        x_s[(cc * 4 + 0) * 64 + nl] = v.x;
        x_s[(cc * 4 + 1) * 64 + nl] = v.y;
        x_s[(cc * 4 + 2) * 64 + nl] = v.z;
        x_s[(cc * 4 + 3) * 64 + nl] = v.w;
    }
    __syncthreads();

    int tn = t >> 4;  // 16 node groups (4 nodes each)
    int td = t & 15;  // 16 dim groups (8 dims each)
    unsigned long long accp[4][4];
#pragma unroll
    for (int i = 0; i < 4; i++)
#pragma unroll
        for (int j = 0; j < 4; j++) accp[i][j] = 0ull;

#pragma unroll 4
    for (int k = 0; k < 64; ++k) {
        const float4 a4 = *(const float4*)(x_s + k * 64 + tn * 4);
        const ulonglong2 w01 = *(const ulonglong2*)(W_s + k * 128 + td * 8);
        const ulonglong2 w23 =
            *(const ulonglong2*)(W_s + k * 128 + td * 8 + 4);
        float aa[4] = {a4.x, a4.y, a4.z, a4.w};
#pragma unroll
        for (int i = 0; i < 4; i++) {
            unsigned long long av;
            DUP2(av, aa[i]);
            FMA2(accp[i][0], av, w01.x);
            FMA2(accp[i][1], av, w01.y);
            FMA2(accp[i][2], av, w23.x);
            FMA2(accp[i][3], av, w23.y);
        }
    }

    float qp[8];
    const float4 q0 = *(const float4*)&g_qpart[b * 128 + td * 8];
    const float4 q1 = *(const float4*)&g_qpart[b * 128 + td * 8 + 4];
    qp[0] = q0.x; qp[1] = q0.y; qp[2] = q0.z; qp[3] = q0.w;
    qp[4] = q1.x; qp[5] = q1.y; qp[6] = q1.z; qp[7] = q1.w;

#pragma unroll
    for (int i = 0; i < 4; i++) {
        float acc[8];
        UNPACK2(acc[0], acc[1], accp[i][0]);
        UNPACK2(acc[2], acc[3], accp[i][1]);
        UNPACK2(acc[4], acc[5], accp[i][2]);
        UNPACK2(acc[6], acc[7], accp[i][3]);
        int n = n0 + tn * 4 + i;
        float* op = out + ((long)(b * NN + n)) * 128 + td * 8;
        float4 o0, o1;
        o0.x = fmaxf(acc[0] + qp[0], 0.f);
        o0.y = fmaxf(acc[1] + qp[1], 0.f);
        o0.z = fmaxf(acc[2] + qp[2], 0.f);
        o0.w = fmaxf(acc[3] + qp[3], 0.f);
        o1.x = fmaxf(acc[4] + qp[4], 0.f);
        o1.y = fmaxf(acc[5] + qp[5], 0.f);
        o1.z = fmaxf(acc[6] + qp[6], 0.f);
        o1.w = fmaxf(acc[7] + qp[7], 0.f);
        *(float4*)op = o0;
        *(float4*)(op + 4) = o1;
    }
}

// ---------------------------------------------------------------------------
extern "C" void kernel_launch(void* const* d_in, const int* in_sizes, int n_in,
                              void* d_out, int out_size) {
    const float* rel_reps = (const float*)d_in[0];
    const int* h_index = (const int*)d_in[1];
    const int* r_index = (const int*)d_in[2];
    const int* edge_index = (const int*)d_in[3];
    const int* edge_type = (const int*)d_in[4];
    const float* pw1 = (const float*)d_in[5];
    const float* pb1 = (const float*)d_in[6];
    const float* pw2 = (const float*)d_in[7];
    const float* pb2 = (const float*)d_in[8];
    const float* lin_w = (const float*)d_in[9];
    const float* lin_b = (const float*)d_in[10];
    const float* ln_g = (const float*)d_in[11];
    const float* ln_b = (const float*)d_in[12];
    const float* mlp_w = (const float*)d_in[13];
    const float* mlp_b = (const float*)d_in[14];
    float* out = (float*)d_out;

    cudaFuncSetAttribute(linear_kernel,
                         cudaFuncAttributeMaxDynamicSharedMemorySize, 65536);
    cudaFuncSetAttribute(final_kernel,
                         cudaFuncAttributeMaxDynamicSharedMemorySize, 49152);

    prep_kernel<<<1, 256>>>(rel_reps, r_index, h_index, mlp_w, mlp_b, lin_b,
                            ln_g, ln_b);
    csr_hist<<<(EE + 255) / 256, 256>>>(edge_index);
    csr_scan1<<<SCANB, 256>>>();
    csr_scan2<<<1, 256>>>();
    csr_scan3<<<SCANB, 256>>>();
    csr_scatter<<<(EE + 255) / 256, 256>>>(edge_index);
    init_x<<<(BB * NN * DD / 4 + 255) / 256, 256>>>(h_index);
    relproj_all<<<LLAYERS * BB * RR, 64>>>(rel_reps, pw1, pb1, pw2, pb2);
    for (int l = 0; l < LLAYERS; l++) {
        gather_kernel<<<BB * NN / 8, 256>>>(edge_index, edge_type, h_index, l);
        linear_kernel<<<dim3((NN + 63) / 64, BB), 256, 65536>>>(lin_w, lin_b,
                                                                ln_g, ln_b, l);
    }
    final_kernel<<<dim3(NN / 64, BB), 256, 49152>>>(mlp_w, out);
}

// round 11
// speedup vs baseline: 1.6413x; 1.0318x over previous
#include <cuda_runtime.h>

#define BB 2
#define NN 40000
#define EE 400000
#define RR 64
#define DD 64
#define LLAYERS 6
#define MASKW 1250   // (NN+31)/32
#define SCANB 157    // (NN+255)/256

#define FMA2(acc, a, b) \
    asm("fma.rn.f32x2 %0, %1, %2, %0;" : "+l"(acc) : "l"(a), "l"(b))
#define PACK2(dst, lo, hi) \
    asm("mov.b64 %0, {%1,%2};" : "=l"(dst) : "r"(__float_as_uint(lo)), "r"(__float_as_uint(hi)))
#define DUP2(dst, v) \
    asm("mov.b64 %0, {%1,%1};" : "=l"(dst) : "r"(__float_as_uint(v)))
#define UNPACK2(lo, hi, src)                          \
    do {                                              \
        unsigned _ulo, _uhi;                          \
        asm("mov.b64 {%0,%1}, %2;"                    \
            : "=r"(_ulo), "=r"(_uhi) : "l"(src));     \
        lo = __uint_as_float(_ulo);                   \
        hi = __uint_as_float(_uhi);                   \
    } while (0)

// Scratch (allocation-free rule: __device__ globals)
__device__ __align__(16) float g_x[BB * NN * DD];    // 20.5 MB
__device__ __align__(16) float g_agg[BB * NN * DD];  // 20.5 MB (listed rows zeroed after each linear)
__device__ __align__(16) float g_rel[LLAYERS * BB * RR * DD];  // all layers upfront
__device__ __align__(16) float g_query[BB * DD];
__device__ __align__(16) float g_qpart[BB * 2 * DD];
__device__ unsigned g_mask[BB * MASKW];  // bit set <=> node is in g_list
__device__ int g_list[BB * NN];          // persistent, monotone across layers
__device__ int g_count[BB];
__device__ int g_dense;  // 1 => zero rows would produce nonzero output
// CSR by dst (shared by both batches — same graph); src/type materialized
__device__ int g_cnt[NN];  // zero at every launch entry/exit (BSS + scan1 restore)
__device__ int g_fill[NN];
__device__ int g_csr_ptr[NN + 1];
__device__ int g_csr_src[EE];
__device__ int g_csr_ty[EE];
__device__ int g_bsum[SCANB + 3];

// ---------------------------------------------------------------------------
// prep: masks, query, dense flag, list seed {h}, qpart
// ---------------------------------------------------------------------------
__global__ void prep_kernel(const float* __restrict__ rel_reps,
                            const int* __restrict__ r_index,
                            const int* __restrict__ h_index,
                            const float* __restrict__ mlp_w,
                            const float* __restrict__ mlp_b,
                            const float* __restrict__ lin_b,
                            const float* __restrict__ ln_g,
                            const float* __restrict__ ln_b) {
    __shared__ float q_s[BB * DD];
    int t = threadIdx.x;  // 256
    for (int i = t; i < BB * MASKW; i += 256) g_mask[i] = 0u;
    if (t < BB * DD) {
        int b = t / DD, d = t % DD;
        float v = rel_reps[(b * RR + r_index[b]) * DD + d];
        g_query[t] = v;
        q_s[t] = v;
    }
    if (t == 0) {
        int dense = 0;
        for (int l = 0; l < LLAYERS; l++) {
            const float* lb = lin_b + l * DD;
            float mu = 0.f;
            for (int d = 0; d < DD; d++) mu += lb[d];
            mu *= (1.f / DD);
            float var = 0.f;
            for (int d = 0; d < DD; d++) {
                float dv = lb[d] - mu;
                var += dv * dv;
            }
            var *= (1.f / DD);
            float inv = rsqrtf(var + 1e-5f);
            for (int d = 0; d < DD; d++) {
                float o = (lb[d] - mu) * inv * ln_g[l * DD + d] + ln_b[l * DD + d];
                if (o > 0.f) dense = 1;
            }
        }
        g_dense = dense;
    }
    __syncthreads();
    if (t < BB) {
        int h = h_index[t];
        g_mask[t * MASKW + (h >> 5)] = 1u << (h & 31);
        g_count[t] = g_dense ? NN : 1;
        g_list[t * NN] = h;
    }
    int b = t / 128, e = t % 128;
    float acc = mlp_b[e];
#pragma unroll
    for (int k = 0; k < DD; k++)
        acc = fmaf(q_s[b * DD + k], mlp_w[(DD + k) * 128 + e], acc);
    g_qpart[b * 128 + e] = acc;
}

// ---------------------------------------------------------------------------
// CSR build. g_cnt is zero at entry (BSS first time; scan1 re-zeroes after).
// ---------------------------------------------------------------------------
__global__ void csr_hist(const int* __restrict__ edge_index) {
    int e = blockIdx.x * 256 + threadIdx.x;
    if (e < EE) atomicAdd(&g_cnt[__ldg(&edge_index[EE + e])], 1);
}
__global__ void csr_scan1() {
    __shared__ int sh[256];
    int t = threadIdx.x;
    int i = blockIdx.x * 256 + t;
    int v = 0;
    if (i < NN) {
        v = g_cnt[i];
        g_cnt[i] = 0;  // restore zero for next launch/replay
    }
    sh[t] = v;
    __syncthreads();
#pragma unroll
    for (int off = 1; off < 256; off <<= 1) {
        int u = (t >= off) ? sh[t - off] : 0;
        __syncthreads();
        sh[t] += u;
        __syncthreads();
    }
    if (t == 255) g_bsum[blockIdx.x] = sh[255];
    if (i < NN) g_csr_ptr[i] = sh[t] - v;
}
// scan of block sums fused into stage 3: every block re-scans 157 ints in smem
__global__ void csr_scan3() {
    __shared__ int sh[256];
    int t = threadIdx.x;
    int v = (t < SCANB) ? g_bsum[t] : 0;
    sh[t] = v;
    __syncthreads();
#pragma unroll
    for (int off = 1; off < 256; off <<= 1) {
        int u = (t >= off) ? sh[t - off] : 0;
        __syncthreads();
        sh[t] += u;
        __syncthreads();
    }
    __shared__ int s_off;
    if (t == 0) s_off = (blockIdx.x == 0) ? 0 : sh[blockIdx.x - 1];
    __syncthreads();
    int i = blockIdx.x * 256 + t;
    if (i < NN) {
        int p = g_csr_ptr[i] + s_off;
        g_csr_ptr[i] = p;
        g_fill[i] = p;
    }
    if (i == 0) g_csr_ptr[NN] = EE;
}
// scatter: also materialize src and type in CSR order (coalesced gather later)
__global__ void csr_scatter(const int* __restrict__ edge_index,
                            const int* __restrict__ edge_type) {
    int e = blockIdx.x * 256 + threadIdx.x;
    if (e >= EE) return;
    int src = __ldg(&edge_index[e]);
    int dst = __ldg(&edge_index[EE + e]);
    int ty = __ldg(&edge_type[e]);
    int pos = atomicAdd(&g_fill[dst], 1);
    g_csr_src[pos] = src;
    g_csr_ty[pos] = ty;
}

// ---------------------------------------------------------------------------
// init x: zeros everywhere, query at h_index[b].
// Dense fallback: identity list + all-ones mask.
// ---------------------------------------------------------------------------
__global__ void init_x(const int* __restrict__ h_index) {
    int gid = blockIdx.x * 256 + threadIdx.x;
    const int per_b = NN * DD / 4;
    if (gid >= BB * per_b) return;
    if (g_dense) {
        if (gid < BB * NN) g_list[gid] = gid % NN;
        if (gid < BB * MASKW) g_mask[gid] = 0xffffffffu;
    }
    int b = gid / per_b;
    int r = gid - b * per_b;
    int n = r >> 4;
    int d4 = r & 15;
    float4 v = make_float4(0.f, 0.f, 0.f, 0.f);
    if (n == __ldg(&h_index[b]))
        v = *(const float4*)&g_query[b * DD + d4 * 4];
    ((float4*)g_x)[gid] = v;
}

// ---------------------------------------------------------------------------
// ALL layers' relation projections in one kernel (depend only on inputs).
// ---------------------------------------------------------------------------
__global__ void relproj_all(const float* __restrict__ rel_reps,
                            const float* __restrict__ pw1,
                            const float* __restrict__ pb1,
                            const float* __restrict__ pw2,
                            const float* __restrict__ pb2) {
    int blk = blockIdx.x;  // l*(BB*RR) + br
    int l = blk / (BB * RR);
    int br = blk - l * (BB * RR);
    int e = threadIdx.x;  // 64
    __shared__ float in_s[DD];
    __shared__ float hid_s[DD];
    in_s[e] = rel_reps[br * DD + e];
    __syncthreads();
    const float* W1 = pw1 + l * DD * DD;
    float acc = pb1[l * DD + e];
#pragma unroll 16
    for (int k = 0; k < DD; k++) acc = fmaf(in_s[k], W1[k * DD + e], acc);
    hid_s[e] = fmaxf(acc, 0.f);
    __syncthreads();
    const float* W2 = pw2 + l * DD * DD;
    float acc2 = pb2[l * DD + e];
#pragma unroll 16
    for (int k = 0; k < DD; k++) acc2 = fmaf(hid_s[k], W2[k * DD + e], acc2);
    g_rel[blk * DD + e] = acc2;
}

// ---------------------------------------------------------------------------
// gather message: warp per (b,dst) — each dst owned by exactly ONE warp.
// src/type read COALESCED from materialized CSR. Active edges accumulate
// x[src]*rel[l,type] via packed f32x2 FMA. New dsts appended to list.
// ---------------------------------------------------------------------------
__global__ void __launch_bounds__(256)
gather_kernel(const int* __restrict__ h_index, int l) {
    const unsigned FULL = 0xffffffffu;
    __shared__ int s_list[8];
    __shared__ int s_n;
    __shared__ int s_base;
    if (threadIdx.x == 0) s_n = 0;
    int w = blockIdx.x * 8 + (threadIdx.x >> 5);  // NN%8==0: block = one batch
    int lane = threadIdx.x & 31;
    int b = (w >= NN) ? 1 : 0;
    int dst = w - b * NN;
    const unsigned* mask = g_mask + b * MASKW;
    const float* relb = g_rel + (l * BB + b) * RR * DD;
    int beg = __ldg(&g_csr_ptr[dst]);
    int end = __ldg(&g_csr_ptr[dst + 1]);
    int h = __ldg(&h_index[b]);
    unsigned long long acc = 0ull;  // packed f32x2
    bool any = false;
    __syncthreads();
    for (int base = beg; base < end; base += 32) {
        int i = base + lane;
        int src = 0, ty = 0;
        bool a = false;
        if (i < end) {
            src = __ldg(&g_csr_src[i]);  // coalesced
            ty = __ldg(&g_csr_ty[i]);    // coalesced
            a = (mask[src >> 5] >> (src & 31)) & 1u;
        }
        unsigned ball = __ballot_sync(FULL, a);
        any |= (ball != 0);
        while (ball) {
            int lx = __ffs(ball) - 1;
            ball &= ball - 1;
            int s = __shfl_sync(FULL, src, lx);
            int tt = __shfl_sync(FULL, ty, lx);
            unsigned long long xv =
                *(const unsigned long long*)&g_x[(b * NN + s) * DD + lane * 2];
            unsigned long long rv =
                *(const unsigned long long*)&relb[tt * DD + lane * 2];
            FMA2(acc, xv, rv);
        }
    }
    float a0, a1;
    UNPACK2(a0, a1, acc);
    if (dst == h) {
        float2 q = *(const float2*)&g_query[b * DD + lane * 2];
        a0 += q.x;
        a1 += q.y;
        any = true;
    }
    if (any) {
        *(float2*)&g_agg[(b * NN + dst) * DD + lane * 2] = make_float2(a0, a1);
        if (lane == 0) {
            unsigned bit = 1u << (dst & 31);
            if (!(mask[dst >> 5] & bit)) {
                unsigned old = atomicOr(&g_mask[b * MASKW + (dst >> 5)], bit);
                if (!(old & bit)) {
                    int p = atomicAdd(&s_n, 1);
                    s_list[p] = dst;
                }
            }
        }
    }
    __syncthreads();
    if (threadIdx.x == 0 && s_n > 0) s_base = atomicAdd(&g_count[b], s_n);
    __syncthreads();
    if ((int)threadIdx.x < s_n)
        g_list[b * NN + s_base + threadIdx.x] = s_list[threadIdx.x];
}

// ---------------------------------------------------------------------------
// fused linear (R3 shape + f32x2): 64 list rows, 256 threads, 4x4 tile.
// ---------------------------------------------------------------------------
__global__ void linear_kernel(const float* __restrict__ lin_w,
                              const float* __restrict__ lin_b,
                              const float* __restrict__ ln_g,
                              const float* __restrict__ ln_b, int l) {
    extern __shared__ float smem[];
    float* W_s = smem;               // [128][64] = 32KB
    float* cat_s = smem + 128 * 64;  // [k][node] transposed = 32KB
    __shared__ int idx_s[64];
    int b = blockIdx.y;
    int base = blockIdx.x * 64;
    int t = threadIdx.x;  // 256
    int cnt = g_count[b];
    if (base >= cnt) return;

    if (t < 64) idx_s[t] = (base + t < cnt) ? g_list[b * NN + base + t] : -1;

    const float4* Wg = (const float4*)(lin_w + l * 128 * 64);
    float4* Ws4 = (float4*)W_s;
#pragma unroll
    for (int i = 0; i < 8; i++) Ws4[t + i * 256] = Wg[t + i * 256];
    __syncthreads();

    int nl = t & 63;
    int c0 = t >> 6;  // 0..3
    int idx = idx_s[nl];
    const float* xb = g_x + (b * NN + idx) * DD;
    const float* ab = g_agg + (b * NN + idx) * DD;
#pragma unroll
    for (int i = 0; i < 4; i++) {
        int cc = c0 + i * 4;  // float4 col 0..15
        float4 v = make_float4(0.f, 0.f, 0.f, 0.f);
        float4 a = make_float4(0.f, 0.f, 0.f, 0.f);
        if (idx >= 0) {
            v = *(const float4*)&xb[cc * 4];
            a = *(const float4*)&ab[cc * 4];
        }
        cat_s[(cc * 4 + 0) * 64 + nl] = v.x;
        cat_s[(cc * 4 + 1) * 64 + nl] = v.y;
        cat_s[(cc * 4 + 2) * 64 + nl] = v.z;
        cat_s[(cc * 4 + 3) * 64 + nl] = v.w;
        cat_s[(64 + cc * 4 + 0) * 64 + nl] = a.x;
        cat_s[(64 + cc * 4 + 1) * 64 + nl] = a.y;
        cat_s[(64 + cc * 4 + 2) * 64 + nl] = a.z;
        cat_s[(64 + cc * 4 + 3) * 64 + nl] = a.w;
    }
    __syncthreads();

    int tn = t >> 4;  // node group (4 nodes)
    int td = t & 15;  // dim group  (4 dims)
    float4 bias4 = *(const float4*)&lin_b[l * 64 + td * 4];
    unsigned long long accp[4][2];
    {
        unsigned long long b01, b23;
        PACK2(b01, bias4.x, bias4.y);
        PACK2(b23, bias4.z, bias4.w);
#pragma unroll
        for (int i = 0; i < 4; i++) {
            accp[i][0] = b01;
            accp[i][1] = b23;
        }
    }

#pragma unroll 4
    for (int k = 0; k < 128; ++k) {
        const float4 a4 = *(const float4*)(cat_s + k * 64 + tn * 4);
        const ulonglong2 w2 = *(const ulonglong2*)(W_s + k * 64 + td * 4);
        float aa[4] = {a4.x, a4.y, a4.z, a4.w};
#pragma unroll
        for (int i = 0; i < 4; i++) {
            unsigned long long av;
            DUP2(av, aa[i]);
            FMA2(accp[i][0], av, w2.x);
            FMA2(accp[i][1], av, w2.y);
        }
    }

    float acc[4][4];
#pragma unroll
    for (int i = 0; i < 4; i++) {
        UNPACK2(acc[i][0], acc[i][1], accp[i][0]);
        UNPACK2(acc[i][2], acc[i][3], accp[i][1]);
    }

    float4 g4 = *(const float4*)&ln_g[l * 64 + td * 4];
    float4 bb4 = *(const float4*)&ln_b[l * 64 + td * 4];
    float lng[4] = {g4.x, g4.y, g4.z, g4.w};
    float lnb[4] = {bb4.x, bb4.y, bb4.z, bb4.w};
#pragma unroll
    for (int i = 0; i < 4; i++) {
        float s = acc[i][0] + acc[i][1] + acc[i][2] + acc[i][3];
        float s2 = acc[i][0] * acc[i][0] + acc[i][1] * acc[i][1] +
                   acc[i][2] * acc[i][2] + acc[i][3] * acc[i][3];
#pragma unroll
        for (int m = 1; m < 16; m <<= 1) {
            s += __shfl_xor_sync(0xffffffffu, s, m);
            s2 += __shfl_xor_sync(0xffffffffu, s2, m);
        }
        float mu = s * (1.f / 64.f);
        float var = s2 * (1.f / 64.f) - mu * mu;
        float inv = rsqrtf(var + 1e-5f);
        int row = idx_s[tn * 4 + i];
        if (row >= 0) {
            float* xr = g_x + (b * NN + row) * DD + td * 4;
            float4 xold = *(const float4*)xr;
            float4 o;
            o.x = fmaxf((acc[i][0] - mu) * inv * lng[0] + lnb[0], 0.f) + xold.x;
            o.y = fmaxf((acc[i][1] - mu) * inv * lng[1] + lnb[1], 0.f) + xold.y;
            o.z = fmaxf((acc[i][2] - mu) * inv * lng[2] + lnb[2], 0.f) + xold.z;
            o.w = fmaxf((acc[i][3] - mu) * inv * lng[3] + lnb[3], 0.f) + xold.w;
            *(float4*)xr = o;
            *(float4*)(g_agg + (b * NN + row) * DD + td * 4) =
                make_float4(0.f, 0.f, 0.f, 0.f);
        }
    }
}

// ---------------------------------------------------------------------------
// final: out = relu([x ; query] @ mlp_w + mlp_b); query part precomputed.
// ---------------------------------------------------------------------------
__global__ void final_kernel(const float* __restrict__ mlp_w,
                             float* __restrict__ out) {
    extern __shared__ float smem[];
    float* W_s = smem;             // [64][128] = 32KB
    float* x_s = smem + 64 * 128;  // [k][node] = 16KB
    int b = blockIdx.y;
    int n0 = blockIdx.x * 64;
    int t = threadIdx.x;

    const float4* Wg = (const float4*)mlp_w;
    float4* Ws4 = (float4*)W_s;
#pragma unroll
    for (int i = 0; i < 8; i++) Ws4[t + i * 256] = Wg[t + i * 256];

    const float* xb = g_x + (b * NN + n0) * DD;
    int nl = t & 63;
    int c0 = t >> 6;
#pragma unroll
    for (int i = 0; i < 4; i++) {
        int cc = c0 + i * 4;
        float4 v = *(const float4*)&xb[nl * DD + cc * 4];
        x_s[(cc * 4 + 0) * 64 + nl] = v.x;
        x_s[(cc * 4 + 1) * 64 + nl] = v.y;
        x_s[(cc * 4 + 2) * 64 + nl] = v.z;
        x_s[(cc * 4 + 3) * 64 + nl] = v.w;
    }
    __syncthreads();

    int tn = t >> 4;  // 16 node groups (4 nodes each)
    int td = t & 15;  // 16 dim groups (8 dims each)
    unsigned long long accp[4][4];
#pragma unroll
    for (int i = 0; i < 4; i++)
#pragma unroll
        for (int j = 0; j < 4; j++) accp[i][j] = 0ull;

#pragma unroll 4
    for (int k = 0; k < 64; ++k) {
        const float4 a4 = *(const float4*)(x_s + k * 64 + tn * 4);
        const ulonglong2 w01 = *(const ulonglong2*)(W_s + k * 128 + td * 8);
        const ulonglong2 w23 =
            *(const ulonglong2*)(W_s + k * 128 + td * 8 + 4);
        float aa[4] = {a4.x, a4.y, a4.z, a4.w};
#pragma unroll
        for (int i = 0; i < 4; i++) {
            unsigned long long av;
            DUP2(av, aa[i]);
            FMA2(accp[i][0], av, w01.x);
            FMA2(accp[i][1], av, w01.y);
            FMA2(accp[i][2], av, w23.x);
            FMA2(accp[i][3], av, w23.y);
        }
    }

    float qp[8];
    const float4 q0 = *(const float4*)&g_qpart[b * 128 + td * 8];
    const float4 q1 = *(const float4*)&g_qpart[b * 128 + td * 8 + 4];
    qp[0] = q0.x; qp[1] = q0.y; qp[2] = q0.z; qp[3] = q0.w;
    qp[4] = q1.x; qp[5] = q1.y; qp[6] = q1.z; qp[7] = q1.w;

#pragma unroll
    for (int i = 0; i < 4; i++) {
        float acc[8];
        UNPACK2(acc[0], acc[1], accp[i][0]);
        UNPACK2(acc[2], acc[3], accp[i][1]);
        UNPACK2(acc[4], acc[5], accp[i][2]);
        UNPACK2(acc[6], acc[7], accp[i][3]);
        int n = n0 + tn * 4 + i;
        float* op = out + ((long)(b * NN + n)) * 128 + td * 8;
        float4 o0, o1;
        o0.x = fmaxf(acc[0] + qp[0], 0.f);
        o0.y = fmaxf(acc[1] + qp[1], 0.f);
        o0.z = fmaxf(acc[2] + qp[2], 0.f);
        o0.w = fmaxf(acc[3] + qp[3], 0.f);
        o1.x = fmaxf(acc[4] + qp[4], 0.f);
        o1.y = fmaxf(acc[5] + qp[5], 0.f);
        o1.z = fmaxf(acc[6] + qp[6], 0.f);
        o1.w = fmaxf(acc[7] + qp[7], 0.f);
        *(float4*)op = o0;
        *(float4*)(op + 4) = o1;
    }
}

// ---------------------------------------------------------------------------
extern "C" void kernel_launch(void* const* d_in, const int* in_sizes, int n_in,
                              void* d_out, int out_size) {
    const float* rel_reps = (const float*)d_in[0];
    const int* h_index = (const int*)d_in[1];
    const int* r_index = (const int*)d_in[2];
    const int* edge_index = (const int*)d_in[3];
    const int* edge_type = (const int*)d_in[4];
    const float* pw1 = (const float*)d_in[5];
    const float* pb1 = (const float*)d_in[6];
    const float* pw2 = (const float*)d_in[7];
    const float* pb2 = (const float*)d_in[8];
    const float* lin_w = (const float*)d_in[9];
    const float* lin_b = (const float*)d_in[10];
    const float* ln_g = (const float*)d_in[11];
    const float* ln_b = (const float*)d_in[12];
    const float* mlp_w = (const float*)d_in[13];
    const float* mlp_b = (const float*)d_in[14];
    float* out = (float*)d_out;

    cudaFuncSetAttribute(linear_kernel,
                         cudaFuncAttributeMaxDynamicSharedMemorySize, 65536);
    cudaFuncSetAttribute(final_kernel,
                         cudaFuncAttributeMaxDynamicSharedMemorySize, 49152);

    prep_kernel<<<1, 256>>>(rel_reps, r_index, h_index, mlp_w, mlp_b, lin_b,
                            ln_g, ln_b);
    csr_hist<<<(EE + 255) / 256, 256>>>(edge_index);
    csr_scan1<<<SCANB, 256>>>();
    csr_scan3<<<SCANB, 256>>>();
    csr_scatter<<<(EE + 255) / 256, 256>>>(edge_index, edge_type);
    init_x<<<(BB * NN * DD / 4 + 255) / 256, 256>>>(h_index);
    relproj_all<<<LLAYERS * BB * RR, 64>>>(rel_reps, pw1, pb1, pw2, pb2);
    for (int l = 0; l < LLAYERS; l++) {
        gather_kernel<<<BB * NN / 8, 256>>>(h_index, l);
        linear_kernel<<<dim3((NN + 63) / 64, BB), 256, 65536>>>(lin_w, lin_b,
                                                                ln_g, ln_b, l);
    }
    final_kernel<<<dim3(NN / 64, BB), 256, 49152>>>(mlp_w, out);
}

// round 12
// speedup vs baseline: 1.7460x; 1.0638x over previous
#include <cuda_runtime.h>

#define BB 2
#define NN 40000
#define EE 400000
#define RR 64
#define DD 64
#define LLAYERS 6
#define MASKW 1250   // (NN+31)/32
#define SCANB 157    // (NN+255)/256

#define FMA2(acc, a, b) \
    asm("fma.rn.f32x2 %0, %1, %2, %0;" : "+l"(acc) : "l"(a), "l"(b))
#define PACK2(dst, lo, hi) \
    asm("mov.b64 %0, {%1,%2};" : "=l"(dst) : "r"(__float_as_uint(lo)), "r"(__float_as_uint(hi)))
#define DUP2(dst, v) \
    asm("mov.b64 %0, {%1,%1};" : "=l"(dst) : "r"(__float_as_uint(v)))
#define UNPACK2(lo, hi, src)                          \
    do {                                              \
        unsigned _ulo, _uhi;                          \
        asm("mov.b64 {%0,%1}, %2;"                    \
            : "=r"(_ulo), "=r"(_uhi) : "l"(src));     \
        lo = __uint_as_float(_ulo);                   \
        hi = __uint_as_float(_uhi);                   \
    } while (0)

// Scratch (allocation-free rule: __device__ globals)
__device__ __align__(16) float g_x[BB * NN * DD];    // 20.5 MB
__device__ __align__(16) float g_agg[BB * NN * DD];  // 20.5 MB (listed rows zeroed after each linear)
__device__ __align__(16) float g_rel[LLAYERS * BB * RR * DD];  // all layers upfront
__device__ __align__(16) float g_query[BB * DD];
__device__ __align__(16) float g_qpart[BB * 2 * DD];
__device__ unsigned g_mask[BB * MASKW];  // bit set <=> node is in g_list
__device__ int g_list[BB * NN];          // persistent, monotone across layers
__device__ int g_count[BB];
__device__ int g_dense;  // 1 => zero rows would produce nonzero output
// CSR by dst (shared by both batches — same graph); src/type materialized
__device__ int g_cnt[NN];  // zero at every launch entry/exit (BSS + scan1 restore)
__device__ int g_fill[NN];
__device__ int g_csr_ptr[NN + 1];
__device__ int g_csr_src[EE];
__device__ int g_csr_ty[EE];
__device__ int g_bsum[SCANB + 3];

// ---------------------------------------------------------------------------
// prep: masks, query, dense flag, list seed {h}, qpart
// ---------------------------------------------------------------------------
__global__ void prep_kernel(const float* __restrict__ rel_reps,
                            const int* __restrict__ r_index,
                            const int* __restrict__ h_index,
                            const float* __restrict__ mlp_w,
                            const float* __restrict__ mlp_b,
                            const float* __restrict__ lin_b,
                            const float* __restrict__ ln_g,
                            const float* __restrict__ ln_b) {
    __shared__ float q_s[BB * DD];
    int t = threadIdx.x;  // 256
    for (int i = t; i < BB * MASKW; i += 256) g_mask[i] = 0u;
    if (t < BB * DD) {
        int b = t / DD, d = t % DD;
        float v = rel_reps[(b * RR + r_index[b]) * DD + d];
        g_query[t] = v;
        q_s[t] = v;
    }
    if (t == 0) {
        int dense = 0;
        for (int l = 0; l < LLAYERS; l++) {
            const float* lb = lin_b + l * DD;
            float mu = 0.f;
            for (int d = 0; d < DD; d++) mu += lb[d];
            mu *= (1.f / DD);
            float var = 0.f;
            for (int d = 0; d < DD; d++) {
                float dv = lb[d] - mu;
                var += dv * dv;
            }
            var *= (1.f / DD);
            float inv = rsqrtf(var + 1e-5f);
            for (int d = 0; d < DD; d++) {
                float o = (lb[d] - mu) * inv * ln_g[l * DD + d] + ln_b[l * DD + d];
                if (o > 0.f) dense = 1;
            }
        }
        g_dense = dense;
    }
    __syncthreads();
    if (t < BB) {
        int h = h_index[t];
        g_mask[t * MASKW + (h >> 5)] = 1u << (h & 31);
        g_count[t] = g_dense ? NN : 1;
        g_list[t * NN] = h;
    }
    int b = t / 128, e = t % 128;
    float acc = mlp_b[e];
#pragma unroll
    for (int k = 0; k < DD; k++)
        acc = fmaf(q_s[b * DD + k], mlp_w[(DD + k) * 128 + e], acc);
    g_qpart[b * 128 + e] = acc;
}

// ---------------------------------------------------------------------------
// CSR build. g_cnt is zero at entry (BSS first time; scan1 restores zero).
// ---------------------------------------------------------------------------
__global__ void csr_hist(const int* __restrict__ edge_index) {
    int e = blockIdx.x * 256 + threadIdx.x;
    if (e < EE) atomicAdd(&g_cnt[__ldg(&edge_index[EE + e])], 1);
}
__global__ void csr_scan1() {
    __shared__ int sh[256];
    int t = threadIdx.x;
    int i = blockIdx.x * 256 + t;
    int v = 0;
    if (i < NN) {
        v = g_cnt[i];
        g_cnt[i] = 0;  // restore zero for next launch/replay
    }
    sh[t] = v;
    __syncthreads();
#pragma unroll
    for (int off = 1; off < 256; off <<= 1) {
        int u = (t >= off) ? sh[t - off] : 0;
        __syncthreads();
        sh[t] += u;
        __syncthreads();
    }
    if (t == 255) g_bsum[blockIdx.x] = sh[255];
    if (i < NN) g_csr_ptr[i] = sh[t] - v;
}
// stage 3: every block re-scans the 157 block-sums in smem, adds offset
__global__ void csr_scan3() {
    __shared__ int sh[256];
    int t = threadIdx.x;
    int v = (t < SCANB) ? g_bsum[t] : 0;
    sh[t] = v;
    __syncthreads();
#pragma unroll
    for (int off = 1; off < 256; off <<= 1) {
        int u = (t >= off) ? sh[t - off] : 0;
        __syncthreads();
        sh[t] += u;
        __syncthreads();
    }
    __shared__ int s_off;
    if (t == 0) s_off = (blockIdx.x == 0) ? 0 : sh[blockIdx.x - 1];
    __syncthreads();
    int i = blockIdx.x * 256 + t;
    if (i < NN) {
        int p = g_csr_ptr[i] + s_off;
        g_csr_ptr[i] = p;
        g_fill[i] = p;
    }
    if (i == 0) g_csr_ptr[NN] = EE;
}
// scatter: materialize src and type in CSR order (coalesced gather later)
__global__ void csr_scatter(const int* __restrict__ edge_index,
                            const int* __restrict__ edge_type) {
    int e = blockIdx.x * 256 + threadIdx.x;
    if (e >= EE) return;
    int src = __ldg(&edge_index[e]);
    int dst = __ldg(&edge_index[EE + e]);
    int ty = __ldg(&edge_type[e]);
    int pos = atomicAdd(&g_fill[dst], 1);
    g_csr_src[pos] = src;
    g_csr_ty[pos] = ty;
}

// ---------------------------------------------------------------------------
// init x: zeros everywhere, query at h_index[b].
// Dense fallback: identity list + all-ones mask.
// ---------------------------------------------------------------------------
__global__ void init_x(const int* __restrict__ h_index) {
    int gid = blockIdx.x * 256 + threadIdx.x;
    const int per_b = NN * DD / 4;
    if (gid >= BB * per_b) return;
    if (g_dense) {
        if (gid < BB * NN) g_list[gid] = gid % NN;
        if (gid < BB * MASKW) g_mask[gid] = 0xffffffffu;
    }
    int b = gid / per_b;
    int r = gid - b * per_b;
    int n = r >> 4;
    int d4 = r & 15;
    float4 v = make_float4(0.f, 0.f, 0.f, 0.f);
    if (n == __ldg(&h_index[b]))
        v = *(const float4*)&g_query[b * DD + d4 * 4];
    ((float4*)g_x)[gid] = v;
}

// ---------------------------------------------------------------------------
// ALL layers' relation projections in one kernel (depend only on inputs).
// ---------------------------------------------------------------------------
__global__ void relproj_all(const float* __restrict__ rel_reps,
                            const float* __restrict__ pw1,
                            const float* __restrict__ pb1,
                            const float* __restrict__ pw2,
                            const float* __restrict__ pb2) {
    int blk = blockIdx.x;  // l*(BB*RR) + br
    int l = blk / (BB * RR);
    int br = blk - l * (BB * RR);
    int e = threadIdx.x;  // 64
    __shared__ float in_s[DD];
    __shared__ float hid_s[DD];
    in_s[e] = rel_reps[br * DD + e];
    __syncthreads();
    const float* W1 = pw1 + l * DD * DD;
    float acc = pb1[l * DD + e];
#pragma unroll 16
    for (int k = 0; k < DD; k++) acc = fmaf(in_s[k], W1[k * DD + e], acc);
    hid_s[e] = fmaxf(acc, 0.f);
    __syncthreads();
    const float* W2 = pw2 + l * DD * DD;
    float acc2 = pb2[l * DD + e];
#pragma unroll 16
    for (int k = 0; k < DD; k++) acc2 = fmaf(hid_s[k], W2[k * DD + e], acc2);
    g_rel[blk * DD + e] = acc2;
}

// ---------------------------------------------------------------------------
// gather message: warp per dst, BOTH batches in one pass (same graph, so
// metadata and probe loop are shared). Coalesced CSR src/type loads; union
// ballot drives predicated per-batch f32x2 accumulation. New dsts appended
// to each batch's persistent list.
// ---------------------------------------------------------------------------
__global__ void __launch_bounds__(256)
gather_kernel(const int* __restrict__ h_index, int l) {
    const unsigned FULL = 0xffffffffu;
    __shared__ int s_list0[8], s_list1[8];
    __shared__ int s_n0, s_n1, s_b0, s_b1;
    if (threadIdx.x == 0) { s_n0 = 0; s_n1 = 0; }
    int dst = blockIdx.x * 8 + (threadIdx.x >> 5);  // NN % 8 == 0
    int lane = threadIdx.x & 31;
    const unsigned* m0 = g_mask;
    const unsigned* m1 = g_mask + MASKW;
    const float* rel0 = g_rel + (l * BB + 0) * RR * DD;
    const float* rel1 = g_rel + (l * BB + 1) * RR * DD;
    int beg = __ldg(&g_csr_ptr[dst]);
    int end = __ldg(&g_csr_ptr[dst + 1]);
    int h0 = __ldg(&h_index[0]);
    int h1 = __ldg(&h_index[1]);
    unsigned long long acc0 = 0ull, acc1 = 0ull;
    bool any0 = false, any1 = false;
    __syncthreads();
    for (int base = beg; base < end; base += 32) {
        int i = base + lane;
        int src = 0, ty = 0;
        bool a0 = false, a1 = false;
        if (i < end) {
            src = __ldg(&g_csr_src[i]);  // coalesced, once for both batches
            ty = __ldg(&g_csr_ty[i]);
            a0 = (m0[src >> 5] >> (src & 31)) & 1u;
            a1 = (m1[src >> 5] >> (src & 31)) & 1u;
        }
        unsigned ball0 = __ballot_sync(FULL, a0);
        unsigned ball1 = __ballot_sync(FULL, a1);
        any0 |= (ball0 != 0);
        any1 |= (ball1 != 0);
        unsigned ball = ball0 | ball1;
        while (ball) {
            int lx = __ffs(ball) - 1;
            ball &= ball - 1;
            int s = __shfl_sync(FULL, src, lx);
            int tt = __shfl_sync(FULL, ty, lx);
            if ((ball0 >> lx) & 1u) {
                unsigned long long xv =
                    *(const unsigned long long*)&g_x[s * DD + lane * 2];
                unsigned long long rv =
                    *(const unsigned long long*)&rel0[tt * DD + lane * 2];
                FMA2(acc0, xv, rv);
            }
            if ((ball1 >> lx) & 1u) {
                unsigned long long xv = *(
                    const unsigned long long*)&g_x[(NN + s) * DD + lane * 2];
                unsigned long long rv =
                    *(const unsigned long long*)&rel1[tt * DD + lane * 2];
                FMA2(acc1, xv, rv);
            }
        }
    }
    float a0x, a0y, a1x, a1y;
    UNPACK2(a0x, a0y, acc0);
    UNPACK2(a1x, a1y, acc1);
    if (dst == h0) {
        float2 q = *(const float2*)&g_query[lane * 2];
        a0x += q.x; a0y += q.y;
        any0 = true;
    }
    if (dst == h1) {
        float2 q = *(const float2*)&g_query[DD + lane * 2];
        a1x += q.x; a1y += q.y;
        any1 = true;
    }
    if (any0) {
        *(float2*)&g_agg[dst * DD + lane * 2] = make_float2(a0x, a0y);
        if (lane == 0) {
            unsigned bit = 1u << (dst & 31);
            if (!(m0[dst >> 5] & bit)) {
                unsigned old = atomicOr(&g_mask[dst >> 5], bit);
                if (!(old & bit)) s_list0[atomicAdd(&s_n0, 1)] = dst;
            }
        }
    }
    if (any1) {
        *(float2*)&g_agg[(NN + dst) * DD + lane * 2] = make_float2(a1x, a1y);
        if (lane == 0) {
            unsigned bit = 1u << (dst & 31);
            if (!(m1[dst >> 5] & bit)) {
                unsigned old = atomicOr(&g_mask[MASKW + (dst >> 5)], bit);
                if (!(old & bit)) s_list1[atomicAdd(&s_n1, 1)] = dst;
            }
        }
    }
    __syncthreads();
    if (threadIdx.x == 0 && s_n0 > 0) s_b0 = atomicAdd(&g_count[0], s_n0);
    if (threadIdx.x == 1 && s_n1 > 0) s_b1 = atomicAdd(&g_count[1], s_n1);
    __syncthreads();
    if ((int)threadIdx.x < s_n0)
        g_list[s_b0 + threadIdx.x] = s_list0[threadIdx.x];
    int t1 = (int)threadIdx.x - 32;
    if (t1 >= 0 && t1 < s_n1) g_list[NN + s_b1 + t1] = s_list1[t1];
}

// ---------------------------------------------------------------------------
// fused linear (R3 shape + f32x2): 64 list rows, 256 threads, 4x4 tile.
// ---------------------------------------------------------------------------
__global__ void linear_kernel(const float* __restrict__ lin_w,
                              const float* __restrict__ lin_b,
                              const float* __restrict__ ln_g,
                              const float* __restrict__ ln_b, int l) {
    extern __shared__ float smem[];
    float* W_s = smem;               // [128][64] = 32KB
    float* cat_s = smem + 128 * 64;  // [k][node] transposed = 32KB
    __shared__ int idx_s[64];
    int b = blockIdx.y;
    int base = blockIdx.x * 64;
    int t = threadIdx.x;  // 256
    int cnt = g_count[b];
    if (base >= cnt) return;

    if (t < 64) idx_s[t] = (base + t < cnt) ? g_list[b * NN + base + t] : -1;

    const float4* Wg = (const float4*)(lin_w + l * 128 * 64);
    float4* Ws4 = (float4*)W_s;
#pragma unroll
    for (int i = 0; i < 8; i++) Ws4[t + i * 256] = Wg[t + i * 256];
    __syncthreads();

    int nl = t & 63;
    int c0 = t >> 6;  // 0..3
    int idx = idx_s[nl];
    const float* xb = g_x + (b * NN + idx) * DD;
    const float* ab = g_agg + (b * NN + idx) * DD;
#pragma unroll
    for (int i = 0; i < 4; i++) {
        int cc = c0 + i * 4;  // float4 col 0..15
        float4 v = make_float4(0.f, 0.f, 0.f, 0.f);
        float4 a = make_float4(0.f, 0.f, 0.f, 0.f);
        if (idx >= 0) {
            v = *(const float4*)&xb[cc * 4];
            a = *(const float4*)&ab[cc * 4];
        }
        cat_s[(cc * 4 + 0) * 64 + nl] = v.x;
        cat_s[(cc * 4 + 1) * 64 + nl] = v.y;
        cat_s[(cc * 4 + 2) * 64 + nl] = v.z;
        cat_s[(cc * 4 + 3) * 64 + nl] = v.w;
        cat_s[(64 + cc * 4 + 0) * 64 + nl] = a.x;
        cat_s[(64 + cc * 4 + 1) * 64 + nl] = a.y;
        cat_s[(64 + cc * 4 + 2) * 64 + nl] = a.z;
        cat_s[(64 + cc * 4 + 3) * 64 + nl] = a.w;
    }
    __syncthreads();

    int tn = t >> 4;  // node group (4 nodes)
    int td = t & 15;  // dim group  (4 dims)
    float4 bias4 = *(const float4*)&lin_b[l * 64 + td * 4];
    unsigned long long accp[4][2];
    {
        unsigned long long b01, b23;
        PACK2(b01, bias4.x, bias4.y);
        PACK2(b23, bias4.z, bias4.w);
#pragma unroll
        for (int i = 0; i < 4; i++) {
            accp[i][0] = b01;
            accp[i][1] = b23;
        }
    }

#pragma unroll 4
    for (int k = 0; k < 128; ++k) {
        const float4 a4 = *(const float4*)(cat_s + k * 64 + tn * 4);
        const ulonglong2 w2 = *(const ulonglong2*)(W_s + k * 64 + td * 4);
        float aa[4] = {a4.x, a4.y, a4.z, a4.w};
#pragma unroll
        for (int i = 0; i < 4; i++) {
            unsigned long long av;
            DUP2(av, aa[i]);
            FMA2(accp[i][0], av, w2.x);
            FMA2(accp[i][1], av, w2.y);
        }
    }

    float acc[4][4];
#pragma unroll
    for (int i = 0; i < 4; i++) {
        UNPACK2(acc[i][0], acc[i][1], accp[i][0]);
        UNPACK2(acc[i][2], acc[i][3], accp[i][1]);
    }

    float4 g4 = *(const float4*)&ln_g[l * 64 + td * 4];
    float4 bb4 = *(const float4*)&ln_b[l * 64 + td * 4];
    float lng[4] = {g4.x, g4.y, g4.z, g4.w};
    float lnb[4] = {bb4.x, bb4.y, bb4.z, bb4.w};
#pragma unroll
    for (int i = 0; i < 4; i++) {
        float s = acc[i][0] + acc[i][1] + acc[i][2] + acc[i][3];
        float s2 = acc[i][0] * acc[i][0] + acc[i][1] * acc[i][1] +
                   acc[i][2] * acc[i][2] + acc[i][3] * acc[i][3];
#pragma unroll
        for (int m = 1; m < 16; m <<= 1) {
            s += __shfl_xor_sync(0xffffffffu, s, m);
            s2 += __shfl_xor_sync(0xffffffffu, s2, m);
        }
        float mu = s * (1.f / 64.f);
        float var = s2 * (1.f / 64.f) - mu * mu;
        float inv = rsqrtf(var + 1e-5f);
        int row = idx_s[tn * 4 + i];
        if (row >= 0) {
            float* xr = g_x + (b * NN + row) * DD + td * 4;
            float4 xold = *(const float4*)xr;
            float4 o;
            o.x = fmaxf((acc[i][0] - mu) * inv * lng[0] + lnb[0], 0.f) + xold.x;
            o.y = fmaxf((acc[i][1] - mu) * inv * lng[1] + lnb[1], 0.f) + xold.y;
            o.z = fmaxf((acc[i][2] - mu) * inv * lng[2] + lnb[2], 0.f) + xold.z;
            o.w = fmaxf((acc[i][3] - mu) * inv * lng[3] + lnb[3], 0.f) + xold.w;
            *(float4*)xr = o;
            *(float4*)(g_agg + (b * NN + row) * DD + td * 4) =
                make_float4(0.f, 0.f, 0.f, 0.f);
        }
    }
}

// ---------------------------------------------------------------------------
// final: out = relu([x ; query] @ mlp_w + mlp_b); query part precomputed.
// ---------------------------------------------------------------------------
__global__ void final_kernel(const float* __restrict__ mlp_w,
                             float* __restrict__ out) {
    extern __shared__ float smem[];
    float* W_s = smem;             // [64][128] = 32KB
    float* x_s = smem + 64 * 128;  // [k][node] = 16KB
    int b = blockIdx.y;
    int n0 = blockIdx.x * 64;
    int t = threadIdx.x;

    const float4* Wg = (const float4*)mlp_w;
    float4* Ws4 = (float4*)W_s;
#pragma unroll
    for (int i = 0; i < 8; i++) Ws4[t + i * 256] = Wg[t + i * 256];

    const float* xb = g_x + (b * NN + n0) * DD;
    int nl = t & 63;
    int c0 = t >> 6;
#pragma unroll
    for (int i = 0; i < 4; i++) {
        int cc = c0 + i * 4;
        float4 v = *(const float4*)&xb[nl * DD + cc * 4];
        x_s[(cc * 4 + 0) * 64 + nl] = v.x;
        x_s[(cc * 4 + 1) * 64 + nl] = v.y;
        x_s[(cc * 4 + 2) * 64 + nl] = v.z;
        x_s[(cc * 4 + 3) * 64 + nl] = v.w;
    }
    __syncthreads();

    int tn = t >> 4;  // 16 node groups (4 nodes each)
    int td = t & 15;  // 16 dim groups (8 dims each)
    unsigned long long accp[4][4];
#pragma unroll
    for (int i = 0; i < 4; i++)
#pragma unroll
        for (int j = 0; j < 4; j++) accp[i][j] = 0ull;

#pragma unroll 4
    for (int k = 0; k < 64; ++k) {
        const float4 a4 = *(const float4*)(x_s + k * 64 + tn * 4);
        const ulonglong2 w01 = *(const ulonglong2*)(W_s + k * 128 + td * 8);
        const ulonglong2 w23 =
            *(const ulonglong2*)(W_s + k * 128 + td * 8 + 4);
        float aa[4] = {a4.x, a4.y, a4.z, a4.w};
#pragma unroll
        for (int i = 0; i < 4; i++) {
            unsigned long long av;
            DUP2(av, aa[i]);
            FMA2(accp[i][0], av, w01.x);
            FMA2(accp[i][1], av, w01.y);
            FMA2(accp[i][2], av, w23.x);
            FMA2(accp[i][3], av, w23.y);
        }
    }

    float qp[8];
    const float4 q0 = *(const float4*)&g_qpart[b * 128 + td * 8];
    const float4 q1 = *(const float4*)&g_qpart[b * 128 + td * 8 + 4];
    qp[0] = q0.x; qp[1] = q0.y; qp[2] = q0.z; qp[3] = q0.w;
    qp[4] = q1.x; qp[5] = q1.y; qp[6] = q1.z; qp[7] = q1.w;

#pragma unroll
    for (int i = 0; i < 4; i++) {
        float acc[8];
        UNPACK2(acc[0], acc[1], accp[i][0]);
        UNPACK2(acc[2], acc[3], accp[i][1]);
        UNPACK2(acc[4], acc[5], accp[i][2]);
        UNPACK2(acc[6], acc[7], accp[i][3]);
        int n = n0 + tn * 4 + i;
        float* op = out + ((long)(b * NN + n)) * 128 + td * 8;
        float4 o0, o1;
        o0.x = fmaxf(acc[0] + qp[0], 0.f);
        o0.y = fmaxf(acc[1] + qp[1], 0.f);
        o0.z = fmaxf(acc[2] + qp[2], 0.f);
        o0.w = fmaxf(acc[3] + qp[3], 0.f);
        o1.x = fmaxf(acc[4] + qp[4], 0.f);
        o1.y = fmaxf(acc[5] + qp[5], 0.f);
        o1.z = fmaxf(acc[6] + qp[6], 0.f);
        o1.w = fmaxf(acc[7] + qp[7], 0.f);
        *(float4*)op = o0;
        *(float4*)(op + 4) = o1;
    }
}

// ---------------------------------------------------------------------------
extern "C" void kernel_launch(void* const* d_in, const int* in_sizes, int n_in,
                              void* d_out, int out_size) {
    const float* rel_reps = (const float*)d_in[0];
    const int* h_index = (const int*)d_in[1];
    const int* r_index = (const int*)d_in[2];
    const int* edge_index = (const int*)d_in[3];
    const int* edge_type = (const int*)d_in[4];
    const float* pw1 = (const float*)d_in[5];
    const float* pb1 = (const float*)d_in[6];
    const float* pw2 = (const float*)d_in[7];
    const float* pb2 = (const float*)d_in[8];
    const float* lin_w = (const float*)d_in[9];
    const float* lin_b = (const float*)d_in[10];
    const float* ln_g = (const float*)d_in[11];
    const float* ln_b = (const float*)d_in[12];
    const float* mlp_w = (const float*)d_in[13];
    const float* mlp_b = (const float*)d_in[14];
    float* out = (float*)d_out;

    cudaFuncSetAttribute(linear_kernel,
                         cudaFuncAttributeMaxDynamicSharedMemorySize, 65536);
    cudaFuncSetAttribute(final_kernel,
                         cudaFuncAttributeMaxDynamicSharedMemorySize, 49152);

    prep_kernel<<<1, 256>>>(rel_reps, r_index, h_index, mlp_w, mlp_b, lin_b,
                            ln_g, ln_b);
    csr_hist<<<(EE + 255) / 256, 256>>>(edge_index);
    csr_scan1<<<SCANB, 256>>>();
    csr_scan3<<<SCANB, 256>>>();
    csr_scatter<<<(EE + 255) / 256, 256>>>(edge_index, edge_type);
    init_x<<<(BB * NN * DD / 4 + 255) / 256, 256>>>(h_index);
    relproj_all<<<LLAYERS * BB * RR, 64>>>(rel_reps, pw1, pb1, pw2, pb2);
    for (int l = 0; l < LLAYERS; l++) {
        gather_kernel<<<NN / 8, 256>>>(h_index, l);
        linear_kernel<<<dim3((NN + 63) / 64, BB), 256, 65536>>>(lin_w, lin_b,
                                                                ln_g, ln_b, l);
    }
    final_kernel<<<dim3(NN / 64, BB), 256, 49152>>>(mlp_w, out);
}

// round 13
// speedup vs baseline: 1.7499x; 1.0022x over previous
#include <cuda_runtime.h>

#define BB 2
#define NN 40000
#define EE 400000
#define RR 64
#define DD 64
#define LLAYERS 6
#define MASKW 1250   // (NN+31)/32
#define SCANB 157    // (NN+255)/256

#define FMA2(acc, a, b) \
    asm("fma.rn.f32x2 %0, %1, %2, %0;" : "+l"(acc) : "l"(a), "l"(b))
#define PACK2(dst, lo, hi) \
    asm("mov.b64 %0, {%1,%2};" : "=l"(dst) : "r"(__float_as_uint(lo)), "r"(__float_as_uint(hi)))
#define DUP2(dst, v) \
    asm("mov.b64 %0, {%1,%1};" : "=l"(dst) : "r"(__float_as_uint(v)))
#define UNPACK2(lo, hi, src)                          \
    do {                                              \
        unsigned _ulo, _uhi;                          \
        asm("mov.b64 {%0,%1}, %2;"                    \
            : "=r"(_ulo), "=r"(_uhi) : "l"(src));     \
        lo = __uint_as_float(_ulo);                   \
        hi = __uint_as_float(_uhi);                   \
    } while (0)

// Scratch (allocation-free rule: __device__ globals)
__device__ __align__(16) float g_x[BB * NN * DD];    // 20.5 MB
__device__ __align__(16) float g_agg[BB * NN * DD];  // gather OVERWRITES rows; listed rows rewritten every layer
__device__ __align__(16) float g_rel[LLAYERS * BB * RR * DD];  // all layers upfront
__device__ __align__(16) float g_query[BB * DD];
__device__ __align__(16) float g_qpart[BB * 2 * DD];
__device__ unsigned g_mask[BB * MASKW];  // bit set <=> node is in g_list
__device__ int g_list[BB * NN];          // persistent, monotone across layers
__device__ int g_count[BB];
__device__ int g_dense;  // 1 => zero rows would produce nonzero output
// CSR by dst (shared by both batches — same graph); {src,ty} materialized
__device__ int g_cnt[NN];  // zero at every launch entry/exit (BSS + scan1 restore)
__device__ int g_fill[NN];
__device__ int g_csr_ptr[NN + 1];
__device__ __align__(16) int2 g_csr_st[EE];  // {src, ty} in CSR order
__device__ int g_bsum[SCANB + 3];

// ---------------------------------------------------------------------------
// prep: masks, query, dense flag, list seed {h}, qpart
// ---------------------------------------------------------------------------
__global__ void prep_kernel(const float* __restrict__ rel_reps,
                            const int* __restrict__ r_index,
                            const int* __restrict__ h_index,
                            const float* __restrict__ mlp_w,
                            const float* __restrict__ mlp_b,
                            const float* __restrict__ lin_b,
                            const float* __restrict__ ln_g,
                            const float* __restrict__ ln_b) {
    __shared__ float q_s[BB * DD];
    int t = threadIdx.x;  // 256
    for (int i = t; i < BB * MASKW; i += 256) g_mask[i] = 0u;
    if (t < BB * DD) {
        int b = t / DD, d = t % DD;
        float v = rel_reps[(b * RR + r_index[b]) * DD + d];
        g_query[t] = v;
        q_s[t] = v;
    }
    if (t == 0) {
        int dense = 0;
        for (int l = 0; l < LLAYERS; l++) {
            const float* lb = lin_b + l * DD;
            float mu = 0.f;
            for (int d = 0; d < DD; d++) mu += lb[d];
            mu *= (1.f / DD);
            float var = 0.f;
            for (int d = 0; d < DD; d++) {
                float dv = lb[d] - mu;
                var += dv * dv;
            }
            var *= (1.f / DD);
            float inv = rsqrtf(var + 1e-5f);
            for (int d = 0; d < DD; d++) {
                float o = (lb[d] - mu) * inv * ln_g[l * DD + d] + ln_b[l * DD + d];
                if (o > 0.f) dense = 1;
            }
        }
        g_dense = dense;
    }
    __syncthreads();
    if (t < BB) {
        int h = h_index[t];
        g_mask[t * MASKW + (h >> 5)] = 1u << (h & 31);
        g_count[t] = g_dense ? NN : 1;
        g_list[t * NN] = h;
    }
    int b = t / 128, e = t % 128;
    float acc = mlp_b[e];
#pragma unroll
    for (int k = 0; k < DD; k++)
        acc = fmaf(q_s[b * DD + k], mlp_w[(DD + k) * 128 + e], acc);
    g_qpart[b * 128 + e] = acc;
}

// ---------------------------------------------------------------------------
// CSR build. g_cnt is zero at entry (BSS first time; scan1 restores zero).
// ---------------------------------------------------------------------------
__global__ void csr_hist(const int* __restrict__ edge_index) {
    int e = blockIdx.x * 256 + threadIdx.x;
    if (e < EE) atomicAdd(&g_cnt[__ldg(&edge_index[EE + e])], 1);
}
__global__ void csr_scan1() {
    __shared__ int sh[256];
    int t = threadIdx.x;
    int i = blockIdx.x * 256 + t;
    int v = 0;
    if (i < NN) {
        v = g_cnt[i];
        g_cnt[i] = 0;  // restore zero for next launch/replay
    }
    sh[t] = v;
    __syncthreads();
#pragma unroll
    for (int off = 1; off < 256; off <<= 1) {
        int u = (t >= off) ? sh[t - off] : 0;
        __syncthreads();
        sh[t] += u;
        __syncthreads();
    }
    if (t == 255) g_bsum[blockIdx.x] = sh[255];
    if (i < NN) g_csr_ptr[i] = sh[t] - v;
}
// stage 3: every block re-scans the 157 block-sums in smem, adds offset
__global__ void csr_scan3() {
    __shared__ int sh[256];
    int t = threadIdx.x;
    int v = (t < SCANB) ? g_bsum[t] : 0;
    sh[t] = v;
    __syncthreads();
#pragma unroll
    for (int off = 1; off < 256; off <<= 1) {
        int u = (t >= off) ? sh[t - off] : 0;
        __syncthreads();
        sh[t] += u;
        __syncthreads();
    }
    __shared__ int s_off;
    if (t == 0) s_off = (blockIdx.x == 0) ? 0 : sh[blockIdx.x - 1];
    __syncthreads();
    int i = blockIdx.x * 256 + t;
    if (i < NN) {
        int p = g_csr_ptr[i] + s_off;
        g_csr_ptr[i] = p;
        g_fill[i] = p;
    }
    if (i == 0) g_csr_ptr[NN] = EE;
}
// scatter: materialize {src,ty} pairs in CSR order (one 8B load in gather)
__global__ void csr_scatter(const int* __restrict__ edge_index,
                            const int* __restrict__ edge_type) {
    int e = blockIdx.x * 256 + threadIdx.x;
    if (e >= EE) return;
    int src = __ldg(&edge_index[e]);
    int dst = __ldg(&edge_index[EE + e]);
    int ty = __ldg(&edge_type[e]);
    int pos = atomicAdd(&g_fill[dst], 1);
    g_csr_st[pos] = make_int2(src, ty);
}

// ---------------------------------------------------------------------------
// init x: zeros everywhere, query at h_index[b].
// Dense fallback: identity list + all-ones mask.
// ---------------------------------------------------------------------------
__global__ void init_x(const int* __restrict__ h_index) {
    int gid = blockIdx.x * 256 + threadIdx.x;
    const int per_b = NN * DD / 4;
    if (gid >= BB * per_b) return;
    if (g_dense) {
        if (gid < BB * NN) g_list[gid] = gid % NN;
        if (gid < BB * MASKW) g_mask[gid] = 0xffffffffu;
    }
    int b = gid / per_b;
    int r = gid - b * per_b;
    int n = r >> 4;
    int d4 = r & 15;
    float4 v = make_float4(0.f, 0.f, 0.f, 0.f);
    if (n == __ldg(&h_index[b]))
        v = *(const float4*)&g_query[b * DD + d4 * 4];
    ((float4*)g_x)[gid] = v;
}

// ---------------------------------------------------------------------------
// ALL layers' relation projections in one kernel (depend only on inputs).
// ---------------------------------------------------------------------------
__global__ void relproj_all(const float* __restrict__ rel_reps,
                            const float* __restrict__ pw1,
                            const float* __restrict__ pb1,
                            const float* __restrict__ pw2,
                            const float* __restrict__ pb2) {
    int blk = blockIdx.x;  // l*(BB*RR) + br
    int l = blk / (BB * RR);
    int br = blk - l * (BB * RR);
    int e = threadIdx.x;  // 64
    __shared__ float in_s[DD];
    __shared__ float hid_s[DD];
    in_s[e] = rel_reps[br * DD + e];
    __syncthreads();
    const float* W1 = pw1 + l * DD * DD;
    float acc = pb1[l * DD + e];
#pragma unroll 16
    for (int k = 0; k < DD; k++) acc = fmaf(in_s[k], W1[k * DD + e], acc);
    hid_s[e] = fmaxf(acc, 0.f);
    __syncthreads();
    const float* W2 = pw2 + l * DD * DD;
    float acc2 = pb2[l * DD + e];
#pragma unroll 16
    for (int k = 0; k < DD; k++) acc2 = fmaf(hid_s[k], W2[k * DD + e], acc2);
    g_rel[blk * DD + e] = acc2;
}

// ---------------------------------------------------------------------------
// gather message: warp per dst, BOTH batches in one pass. One coalesced 8B
// {src,ty} load per edge; union ballot drives predicated per-batch f32x2
// accumulation. Rows are OVERWRITTEN (no agg zeroing needed anywhere).
// ---------------------------------------------------------------------------
__global__ void __launch_bounds__(256)
gather_kernel(const int* __restrict__ h_index, int l) {
    const unsigned FULL = 0xffffffffu;
    __shared__ int s_list0[8], s_list1[8];
    __shared__ int s_n0, s_n1, s_b0, s_b1;
    if (threadIdx.x == 0) { s_n0 = 0; s_n1 = 0; }
    int dst = blockIdx.x * 8 + (threadIdx.x >> 5);  // NN % 8 == 0
    int lane = threadIdx.x & 31;
    const unsigned* m0 = g_mask;
    const unsigned* m1 = g_mask + MASKW;
    const float* rel0 = g_rel + (l * BB + 0) * RR * DD;
    const float* rel1 = g_rel + (l * BB + 1) * RR * DD;
    int beg = __ldg(&g_csr_ptr[dst]);
    int end = __ldg(&g_csr_ptr[dst + 1]);
    int h0 = __ldg(&h_index[0]);
    int h1 = __ldg(&h_index[1]);
    unsigned long long acc0 = 0ull, acc1 = 0ull;
    bool any0 = false, any1 = false;
    __syncthreads();
    for (int base = beg; base < end; base += 32) {
        int i = base + lane;
        int src = 0, ty = 0;
        bool a0 = false, a1 = false;
        if (i < end) {
            int2 st = __ldg(&g_csr_st[i]);  // one coalesced 8B load
            src = st.x;
            ty = st.y;
            a0 = (m0[src >> 5] >> (src & 31)) & 1u;
            a1 = (m1[src >> 5] >> (src & 31)) & 1u;
        }
        unsigned ball0 = __ballot_sync(FULL, a0);
        unsigned ball1 = __ballot_sync(FULL, a1);
        any0 |= (ball0 != 0);
        any1 |= (ball1 != 0);
        unsigned ball = ball0 | ball1;
        while (ball) {
            int lx = __ffs(ball) - 1;
            ball &= ball - 1;
            int s = __shfl_sync(FULL, src, lx);
            int tt = __shfl_sync(FULL, ty, lx);
            if ((ball0 >> lx) & 1u) {
                unsigned long long xv =
                    *(const unsigned long long*)&g_x[s * DD + lane * 2];
                unsigned long long rv =
                    *(const unsigned long long*)&rel0[tt * DD + lane * 2];
                FMA2(acc0, xv, rv);
            }
            if ((ball1 >> lx) & 1u) {
                unsigned long long xv = *(
                    const unsigned long long*)&g_x[(NN + s) * DD + lane * 2];
                unsigned long long rv =
                    *(const unsigned long long*)&rel1[tt * DD + lane * 2];
                FMA2(acc1, xv, rv);
            }
        }
    }
    float a0x, a0y, a1x, a1y;
    UNPACK2(a0x, a0y, acc0);
    UNPACK2(a1x, a1y, acc1);
    if (dst == h0) {
        float2 q = *(const float2*)&g_query[lane * 2];
        a0x += q.x; a0y += q.y;
        any0 = true;
    }
    if (dst == h1) {
        float2 q = *(const float2*)&g_query[DD + lane * 2];
        a1x += q.x; a1y += q.y;
        any1 = true;
    }
    if (any0) {
        *(float2*)&g_agg[dst * DD + lane * 2] = make_float2(a0x, a0y);
        if (lane == 0) {
            unsigned bit = 1u << (dst & 31);
            if (!(m0[dst >> 5] & bit)) {
                unsigned old = atomicOr(&g_mask[dst >> 5], bit);
                if (!(old & bit)) s_list0[atomicAdd(&s_n0, 1)] = dst;
            }
        }
    }
    if (any1) {
        *(float2*)&g_agg[(NN + dst) * DD + lane * 2] = make_float2(a1x, a1y);
        if (lane == 0) {
            unsigned bit = 1u << (dst & 31);
            if (!(m1[dst >> 5] & bit)) {
                unsigned old = atomicOr(&g_mask[MASKW + (dst >> 5)], bit);
                if (!(old & bit)) s_list1[atomicAdd(&s_n1, 1)] = dst;
            }
        }
    }
    __syncthreads();
    if (threadIdx.x == 0 && s_n0 > 0) s_b0 = atomicAdd(&g_count[0], s_n0);
    if (threadIdx.x == 1 && s_n1 > 0) s_b1 = atomicAdd(&g_count[1], s_n1);
    __syncthreads();
    if ((int)threadIdx.x < s_n0)
        g_list[s_b0 + threadIdx.x] = s_list0[threadIdx.x];
    int t1 = (int)threadIdx.x - 32;
    if (t1 >= 0 && t1 < s_n1) g_list[NN + s_b1 + t1] = s_list1[t1];
}

// ---------------------------------------------------------------------------
// fused linear (R3 shape + f32x2): 64 list rows, 256 threads, 4x4 tile.
// NOTE: no agg zeroing — gather overwrites listed rows every layer.
// ---------------------------------------------------------------------------
__global__ void linear_kernel(const float* __restrict__ lin_w,
                              const float* __restrict__ lin_b,
                              const float* __restrict__ ln_g,
                              const float* __restrict__ ln_b, int l) {
    extern __shared__ float smem[];
    float* W_s = smem;               // [128][64] = 32KB
    float* cat_s = smem + 128 * 64;  // [k][node] transposed = 32KB
    __shared__ int idx_s[64];
    int b = blockIdx.y;
    int base = blockIdx.x * 64;
    int t = threadIdx.x;  // 256
    int cnt = g_count[b];
    if (base >= cnt) return;

    if (t < 64) idx_s[t] = (base + t < cnt) ? g_list[b * NN + base + t] : -1;

    const float4* Wg = (const float4*)(lin_w + l * 128 * 64);
    float4* Ws4 = (float4*)W_s;
#pragma unroll
    for (int i = 0; i < 8; i++) Ws4[t + i * 256] = Wg[t + i * 256];
    __syncthreads();

    int nl = t & 63;
    int c0 = t >> 6;  // 0..3
    int idx = idx_s[nl];
    const float* xb = g_x + (b * NN + idx) * DD;
    const float* ab = g_agg + (b * NN + idx) * DD;
#pragma unroll
    for (int i = 0; i < 4; i++) {
        int cc = c0 + i * 4;  // float4 col 0..15
        float4 v = make_float4(0.f, 0.f, 0.f, 0.f);
        float4 a = make_float4(0.f, 0.f, 0.f, 0.f);
        if (idx >= 0) {
            v = *(const float4*)&xb[cc * 4];
            a = *(const float4*)&ab[cc * 4];
        }
        cat_s[(cc * 4 + 0) * 64 + nl] = v.x;
        cat_s[(cc * 4 + 1) * 64 + nl] = v.y;
        cat_s[(cc * 4 + 2) * 64 + nl] = v.z;
        cat_s[(cc * 4 + 3) * 64 + nl] = v.w;
        cat_s[(64 + cc * 4 + 0) * 64 + nl] = a.x;
        cat_s[(64 + cc * 4 + 1) * 64 + nl] = a.y;
        cat_s[(64 + cc * 4 + 2) * 64 + nl] = a.z;
        cat_s[(64 + cc * 4 + 3) * 64 + nl] = a.w;
    }
    __syncthreads();

    int tn = t >> 4;  // node group (4 nodes)
    int td = t & 15;  // dim group  (4 dims)
    float4 bias4 = *(const float4*)&lin_b[l * 64 + td * 4];
    unsigned long long accp[4][2];
    {
        unsigned long long b01, b23;
        PACK2(b01, bias4.x, bias4.y);
        PACK2(b23, bias4.z, bias4.w);
#pragma unroll
        for (int i = 0; i < 4; i++) {
            accp[i][0] = b01;
            accp[i][1] = b23;
        }
    }

#pragma unroll 4
    for (int k = 0; k < 128; ++k) {
        const float4 a4 = *(const float4*)(cat_s + k * 64 + tn * 4);
        const ulonglong2 w2 = *(const ulonglong2*)(W_s + k * 64 + td * 4);
        float aa[4] = {a4.x, a4.y, a4.z, a4.w};
#pragma unroll
        for (int i = 0; i < 4; i++) {
            unsigned long long av;
            DUP2(av, aa[i]);
            FMA2(accp[i][0], av, w2.x);
            FMA2(accp[i][1], av, w2.y);
        }
    }

    float acc[4][4];
#pragma unroll
    for (int i = 0; i < 4; i++) {
        UNPACK2(acc[i][0], acc[i][1], accp[i][0]);
        UNPACK2(acc[i][2], acc[i][3], accp[i][1]);
    }

    float4 g4 = *(const float4*)&ln_g[l * 64 + td * 4];
    float4 bb4 = *(const float4*)&ln_b[l * 64 + td * 4];
    float lng[4] = {g4.x, g4.y, g4.z, g4.w};
    float lnb[4] = {bb4.x, bb4.y, bb4.z, bb4.w};
#pragma unroll
    for (int i = 0; i < 4; i++) {
        float s = acc[i][0] + acc[i][1] + acc[i][2] + acc[i][3];
        float s2 = acc[i][0] * acc[i][0] + acc[i][1] * acc[i][1] +
                   acc[i][2] * acc[i][2] + acc[i][3] * acc[i][3];
#pragma unroll
        for (int m = 1; m < 16; m <<= 1) {
            s += __shfl_xor_sync(0xffffffffu, s, m);
            s2 += __shfl_xor_sync(0xffffffffu, s2, m);
        }
        float mu = s * (1.f / 64.f);
        float var = s2 * (1.f / 64.f) - mu * mu;
        float inv = rsqrtf(var + 1e-5f);
        int row = idx_s[tn * 4 + i];
        if (row >= 0) {
            float* xr = g_x + (b * NN + row) * DD + td * 4;
            float4 xold = *(const float4*)xr;
            float4 o;
            o.x = fmaxf((acc[i][0] - mu) * inv * lng[0] + lnb[0], 0.f) + xold.x;
            o.y = fmaxf((acc[i][1] - mu) * inv * lng[1] + lnb[1], 0.f) + xold.y;
            o.z = fmaxf((acc[i][2] - mu) * inv * lng[2] + lnb[2], 0.f) + xold.z;
            o.w = fmaxf((acc[i][3] - mu) * inv * lng[3] + lnb[3], 0.f) + xold.w;
            *(float4*)xr = o;
        }
    }
}

// ---------------------------------------------------------------------------
// final: out = relu([x ; query] @ mlp_w + mlp_b); query part precomputed.
// ---------------------------------------------------------------------------
__global__ void final_kernel(const float* __restrict__ mlp_w,
                             float* __restrict__ out) {
    extern __shared__ float smem[];
    float* W_s = smem;             // [64][128] = 32KB
    float* x_s = smem + 64 * 128;  // [k][node] = 16KB
    int b = blockIdx.y;
    int n0 = blockIdx.x * 64;
    int t = threadIdx.x;

    const float4* Wg = (const float4*)mlp_w;
    float4* Ws4 = (float4*)W_s;
#pragma unroll
    for (int i = 0; i < 8; i++) Ws4[t + i * 256] = Wg[t + i * 256];

    const float* xb = g_x + (b * NN + n0) * DD;
    int nl = t & 63;
    int c0 = t >> 6;
#pragma unroll
    for (int i = 0; i < 4; i++) {
        int cc = c0 + i * 4;
        float4 v = *(const float4*)&xb[nl * DD + cc * 4];
        x_s[(cc * 4 + 0) * 64 + nl] = v.x;
        x_s[(cc * 4 + 1) * 64 + nl] = v.y;
        x_s[(cc * 4 + 2) * 64 + nl] = v.z;
        x_s[(cc * 4 + 3) * 64 + nl] = v.w;
    }
    __syncthreads();

    int tn = t >> 4;  // 16 node groups (4 nodes each)
    int td = t & 15;  // 16 dim groups (8 dims each)
    unsigned long long accp[4][4];
#pragma unroll
    for (int i = 0; i < 4; i++)
#pragma unroll
        for (int j = 0; j < 4; j++) accp[i][j] = 0ull;

#pragma unroll 4
    for (int k = 0; k < 64; ++k) {
        const float4 a4 = *(const float4*)(x_s + k * 64 + tn * 4);
        const ulonglong2 w01 = *(const ulonglong2*)(W_s + k * 128 + td * 8);
        const ulonglong2 w23 =
            *(const ulonglong2*)(W_s + k * 128 + td * 8 + 4);
        float aa[4] = {a4.x, a4.y, a4.z, a4.w};
#pragma unroll
        for (int i = 0; i < 4; i++) {
            unsigned long long av;
            DUP2(av, aa[i]);
            FMA2(accp[i][0], av, w01.x);
            FMA2(accp[i][1], av, w01.y);
            FMA2(accp[i][2], av, w23.x);
            FMA2(accp[i][3], av, w23.y);
        }
    }

    float qp[8];
    const float4 q0 = *(const float4*)&g_qpart[b * 128 + td * 8];
    const float4 q1 = *(const float4*)&g_qpart[b * 128 + td * 8 + 4];
    qp[0] = q0.x; qp[1] = q0.y; qp[2] = q0.z; qp[3] = q0.w;
    qp[4] = q1.x; qp[5] = q1.y; qp[6] = q1.z; qp[7] = q1.w;

#pragma unroll
    for (int i = 0; i < 4; i++) {
        float acc[8];
        UNPACK2(acc[0], acc[1], accp[i][0]);
        UNPACK2(acc[2], acc[3], accp[i][1]);
        UNPACK2(acc[4], acc[5], accp[i][2]);
        UNPACK2(acc[6], acc[7], accp[i][3]);
        int n = n0 + tn * 4 + i;
        float* op = out + ((long)(b * NN + n)) * 128 + td * 8;
        float4 o0, o1;
        o0.x = fmaxf(acc[0] + qp[0], 0.f);
        o0.y = fmaxf(acc[1] + qp[1], 0.f);
        o0.z = fmaxf(acc[2] + qp[2], 0.f);
        o0.w = fmaxf(acc[3] + qp[3], 0.f);
        o1.x = fmaxf(acc[4] + qp[4], 0.f);
        o1.y = fmaxf(acc[5] + qp[5], 0.f);
        o1.z = fmaxf(acc[6] + qp[6], 0.f);
        o1.w = fmaxf(acc[7] + qp[7], 0.f);
        *(float4*)op = o0;
        *(float4*)(op + 4) = o1;
    }
}

// ---------------------------------------------------------------------------
extern "C" void kernel_launch(void* const* d_in, const int* in_sizes, int n_in,
                              void* d_out, int out_size) {
    const float* rel_reps = (const float*)d_in[0];
    const int* h_index = (const int*)d_in[1];
    const int* r_index = (const int*)d_in[2];
    const int* edge_index = (const int*)d_in[3];
    const int* edge_type = (const int*)d_in[4];
    const float* pw1 = (const float*)d_in[5];
    const float* pb1 = (const float*)d_in[6];
    const float* pw2 = (const float*)d_in[7];
    const float* pb2 = (const float*)d_in[8];
    const float* lin_w = (const float*)d_in[9];
    const float* lin_b = (const float*)d_in[10];
    const float* ln_g = (const float*)d_in[11];
    const float* ln_b = (const float*)d_in[12];
    const float* mlp_w = (const float*)d_in[13];
    const float* mlp_b = (const float*)d_in[14];
    float* out = (float*)d_out;

    cudaFuncSetAttribute(linear_kernel,
                         cudaFuncAttributeMaxDynamicSharedMemorySize, 65536);
    cudaFuncSetAttribute(final_kernel,
                         cudaFuncAttributeMaxDynamicSharedMemorySize, 49152);

    prep_kernel<<<1, 256>>>(rel_reps, r_index, h_index, mlp_w, mlp_b, lin_b,
                            ln_g, ln_b);
    csr_hist<<<(EE + 255) / 256, 256>>>(edge_index);
    csr_scan1<<<SCANB, 256>>>();
    csr_scan3<<<SCANB, 256>>>();
    csr_scatter<<<(EE + 255) / 256, 256>>>(edge_index, edge_type);
    init_x<<<(BB * NN * DD / 4 + 255) / 256, 256>>>(h_index);
    relproj_all<<<LLAYERS * BB * RR, 64>>>(rel_reps, pw1, pb1, pw2, pb2);
    for (int l = 0; l < LLAYERS; l++) {
        gather_kernel<<<NN / 8, 256>>>(h_index, l);
        linear_kernel<<<dim3((NN + 63) / 64, BB), 256, 65536>>>(lin_w, lin_b,
                                                                ln_g, ln_b, l);
    }
    final_kernel<<<dim3(NN / 64, BB), 256, 49152>>>(mlp_w, out);
}